// round 1
// baseline (speedup 1.0000x reference)
#include <cuda_runtime.h>
#include <math.h>

#define T_  1024
#define B_  8
#define C_  1024
#define H_  16
#define D_  64
#define M_  4096
#define TA_ 1024
#define R_  (T_*B_)      // 8192 rows (t,b)
#define SIXC (6*C_)

// ---------------- scratch (device globals; no allocation allowed) -----------
__device__ float g_mod[B_*SIXC];          // adaLN params [B, 6C]
__device__ float g_ln [R_*C_];            // ln+modulate output
__device__ float g_q  [R_*C_];
__device__ float g_k  [R_*C_];
__device__ float g_v  [R_*C_];
__device__ float g_y  [R_*C_];            // attention output (pre-proj)
__device__ float g_h  [(size_t)R_*M_];    // mlp hidden (128 MB)

// ---------------- helpers ----------------------------------------------------
__device__ __forceinline__ float gelu_tanh(float x) {
    float x3 = x*x*x;
    return 0.5f*x*(1.f + tanhf(0.7978845608028654f*(x + 0.044715f*x3)));
}

// ---------------- copy x -> out ----------------------------------------------
__global__ void copy_k(const float* __restrict__ in, float* __restrict__ out) {
    int i = blockIdx.x*blockDim.x + threadIdx.x;
    ((float4*)out)[i] = ((const float4*)in)[i];
}

// ---------------- mod = silu(c) @ w_ada + b_ada  [B,6C] ----------------------
__global__ void mod_k(const float* __restrict__ c, const float* __restrict__ w,
                      const float* __restrict__ bias, float* __restrict__ mod) {
    __shared__ float sc[B_][C_];
    int tid = threadIdx.x;
    for (int i = tid; i < B_*C_; i += 256) {
        float v = c[i];
        sc[i>>10][i&1023] = v / (1.f + __expf(-v));
    }
    __syncthreads();
    int col = blockIdx.x*256 + tid;
    float acc[B_];
    #pragma unroll
    for (int b = 0; b < B_; b++) acc[b] = 0.f;
    for (int k = 0; k < C_; k++) {
        float wv = w[(size_t)k*SIXC + col];
        #pragma unroll
        for (int b = 0; b < B_; b++) acc[b] += sc[b][k]*wv;
    }
    float bb = bias[col];
    #pragma unroll
    for (int b = 0; b < B_; b++) mod[b*SIXC + col] = acc[b] + bb;
}

// ---------------- LN (no affine) + modulate ----------------------------------
// row = t*B + b ; shift/scale at mod[b*6C + off + c]
__global__ void ln_mod_k(const float* __restrict__ x, const float* __restrict__ mod,
                         int shiftOff, int scaleOff, float* __restrict__ out) {
    int row = blockIdx.x;
    int b   = row & (B_-1);
    const float* xr = x + (size_t)row*C_;
    float s = 0.f, s2 = 0.f;
    for (int i = threadIdx.x; i < C_; i += 256) {
        float v = xr[i]; s += v; s2 += v*v;
    }
    #pragma unroll
    for (int o = 16; o; o >>= 1) {
        s  += __shfl_xor_sync(0xffffffffu, s,  o);
        s2 += __shfl_xor_sync(0xffffffffu, s2, o);
    }
    __shared__ float red[2][8];
    int w = threadIdx.x >> 5, ln = threadIdx.x & 31;
    if (ln == 0) { red[0][w] = s; red[1][w] = s2; }
    __syncthreads();
    s = 0.f; s2 = 0.f;
    #pragma unroll
    for (int i = 0; i < 8; i++) { s += red[0][i]; s2 += red[1][i]; }
    float mu   = s * (1.f/C_);
    float var  = s2 * (1.f/C_) - mu*mu;
    float rstd = rsqrtf(var + 1e-6f);
    const float* sh = mod + b*SIXC + shiftOff;
    const float* sc = mod + b*SIXC + scaleOff;
    float* orow = out + (size_t)row*C_;
    for (int i = threadIdx.x; i < C_; i += 256)
        orow[i] = (xr[i]-mu)*rstd*(1.f+sc[i]) + sh[i];
}

// ---------------- tiled SGEMM 128x128x8, 256 thr, 8x8 micro-tile -------------
// out = A[R,K] @ W[K,N] (+ epilogue).  EPI: 0 bias, 1 bias+gelu, 2 out += gate*(v+bias)
template<int EPI>
__global__ void sgemm_k(const float* __restrict__ A, const float* __restrict__ W,
                        const float* __restrict__ bias, float* __restrict__ out,
                        const float* __restrict__ gate, int K, int N) {
    __shared__ float As[8][128];
    __shared__ float Bs[8][128];
    int tid  = threadIdx.x;
    int row0 = blockIdx.y*128;
    int col0 = blockIdx.x*128;
    int arow = tid >> 1, acol = (tid & 1)*4;
    int brow = tid >> 5, bcol = (tid & 31)*4;
    const float* Ap = A + (size_t)(row0+arow)*K + acol;
    const float* Wp = W + (size_t)brow*N + col0 + bcol;
    float acc[8][8];
    #pragma unroll
    for (int i = 0; i < 8; i++)
        #pragma unroll
        for (int j = 0; j < 8; j++) acc[i][j] = 0.f;
    int ty = tid >> 4, tx = tid & 15;

    for (int k0 = 0; k0 < K; k0 += 8) {
        float4 av = *(const float4*)Ap;  Ap += 8;
        float4 bv = *(const float4*)Wp;  Wp += (size_t)8*N;
        __syncthreads();
        As[acol+0][arow] = av.x; As[acol+1][arow] = av.y;
        As[acol+2][arow] = av.z; As[acol+3][arow] = av.w;
        *(float4*)&Bs[brow][bcol] = bv;
        __syncthreads();
        #pragma unroll
        for (int kk = 0; kk < 8; kk++) {
            float a[8], bvv[8];
            #pragma unroll
            for (int i = 0; i < 8; i++) a[i]   = As[kk][ty*8+i];
            #pragma unroll
            for (int j = 0; j < 8; j++) bvv[j] = Bs[kk][tx*8+j];
            #pragma unroll
            for (int i = 0; i < 8; i++)
                #pragma unroll
                for (int j = 0; j < 8; j++) acc[i][j] += a[i]*bvv[j];
        }
    }
    #pragma unroll
    for (int i = 0; i < 8; i++) {
        int r  = row0 + ty*8 + i;
        int bb = r & (B_-1);
        float* orow = out + (size_t)r*N;
        #pragma unroll
        for (int j = 0; j < 8; j++) {
            int cidx = col0 + tx*8 + j;
            float v = acc[i][j] + bias[cidx];
            if (EPI == 0)      orow[cidx] = v;
            else if (EPI == 1) orow[cidx] = gelu_tanh(v);
            else               orow[cidx] += gate[bb*SIXC + cidx]*v;
        }
    }
}

// ---------------- flash attention --------------------------------------------
// Q rows [T,B,C]; K/V rows [Tk,B,C]; mask [B,Tk] (nonzero = masked out)
// grid (T/64, H, B), 256 threads. Thread (r=tid/4, g=tid%4) owns row r, cols g*16..+15.
#define ASTR 65
__global__ void attn_k(const float* __restrict__ Q, const float* __restrict__ Kx,
                       const float* __restrict__ Vx, const int* __restrict__ mask,
                       float* __restrict__ Y, int Tk) {
    extern __shared__ float sm[];
    float* Qs = sm;
    float* Ks = Qs + 64*ASTR;
    float* Vs = Ks + 64*ASTR;
    float* Ss = Vs + 64*ASTR;
    int*   Ms = (int*)(Ss + 64*ASTR);

    int tid = threadIdx.x;
    int q0 = blockIdx.x*64, h = blockIdx.y, b = blockIdx.z;
    size_t hoff = (size_t)h*D_;

    for (int i = tid; i < 64*64; i += 256) {
        int r = i >> 6, d = i & 63;
        Qs[r*ASTR + d] = Q[((size_t)(q0+r)*B_ + b)*C_ + hoff + d];
    }
    int r = tid >> 2, g = tid & 3, c0 = g*16;
    float m = -1e30f, l = 0.f;
    float acc[16];
    #pragma unroll
    for (int i = 0; i < 16; i++) acc[i] = 0.f;
    __syncthreads();

    for (int k0 = 0; k0 < Tk; k0 += 64) {
        for (int i = tid; i < 64*64; i += 256) {
            int rr = i >> 6, d = i & 63;
            size_t gi = ((size_t)(k0+rr)*B_ + b)*C_ + hoff + d;
            Ks[rr*ASTR + d] = Kx[gi];
            Vs[rr*ASTR + d] = Vx[gi];
        }
        if (tid < 64) Ms[tid] = mask[(size_t)b*Tk + k0 + tid];
        __syncthreads();

        // S = Q K^T * 0.125 (masked -> -1e30)
        float sv[16];
        #pragma unroll
        for (int j = 0; j < 16; j++) sv[j] = 0.f;
        #pragma unroll 8
        for (int kk = 0; kk < 64; kk++) {
            float qv = Qs[r*ASTR + kk];
            #pragma unroll
            for (int j = 0; j < 16; j++) sv[j] += qv*Ks[(c0+j)*ASTR + kk];
        }
        #pragma unroll
        for (int j = 0; j < 16; j++)
            Ss[r*ASTR + c0 + j] = Ms[c0+j] ? -1e30f : sv[j]*0.125f;
        __syncthreads();

        // row max (each of 4 row-threads computes identically)
        float mnew = m;
        #pragma unroll 8
        for (int j = 0; j < 64; j++) mnew = fmaxf(mnew, Ss[r*ASTR + j]);
        float scale = __expf(m - mnew);
        m = mnew;
        __syncthreads();   // everyone done reading raw S before in-place P write

        // P (own 16 cols), exp computed once per score
        #pragma unroll
        for (int j = 0; j < 16; j++) {
            float s = Ss[r*ASTR + c0 + j];
            Ss[r*ASTR + c0 + j] = (s > -1e29f) ? __expf(s - mnew) : 0.f;
        }
        __syncthreads();

        // rescale + P@V + row sum
        l *= scale;
        #pragma unroll
        for (int i = 0; i < 16; i++) acc[i] *= scale;
        float rs = 0.f;
        #pragma unroll 4
        for (int j = 0; j < 64; j++) {
            float p = Ss[r*ASTR + j];
            rs += p;
            #pragma unroll
            for (int cc = 0; cc < 16; cc++) acc[cc] += p*Vs[j*ASTR + c0 + cc];
        }
        l += rs;
        __syncthreads();   // PV done before next tile overwrites Ks/Vs/Ss
    }
    float inv = 1.f/l;
    size_t obase = ((size_t)(q0+r)*B_ + b)*C_ + hoff + c0;
    #pragma unroll
    for (int cc = 0; cc < 16; cc++) Y[obase + cc] = acc[cc]*inv;
}

// ---------------- launch -----------------------------------------------------
extern "C" void kernel_launch(void* const* d_in, const int* in_sizes, int n_in,
                              void* d_out, int out_size) {
    const float* x     = (const float*)d_in[0];
    const float* c     = (const float*)d_in[1];
    const int*   pmask = (const int*)  d_in[2];
    const float* audio = (const float*)d_in[3];
    const int*   amask = (const int*)  d_in[4];
    const float* w_ada = (const float*)d_in[5];
    const float* b_ada = (const float*)d_in[6];
    const float* wq = (const float*)d_in[7];   const float* bq = (const float*)d_in[8];
    const float* wk = (const float*)d_in[9];   const float* bk = (const float*)d_in[10];
    const float* wv = (const float*)d_in[11];  const float* bv = (const float*)d_in[12];
    const float* wo = (const float*)d_in[13];  const float* bo = (const float*)d_in[14];
    const float* cwq = (const float*)d_in[15]; const float* cbq = (const float*)d_in[16];
    const float* cwk = (const float*)d_in[17]; const float* cbk = (const float*)d_in[18];
    const float* cwv = (const float*)d_in[19]; const float* cbv = (const float*)d_in[20];
    const float* cwo = (const float*)d_in[21]; const float* cbo = (const float*)d_in[22];
    const float* w1 = (const float*)d_in[23];  const float* b1 = (const float*)d_in[24];
    const float* w2 = (const float*)d_in[25];  const float* b2 = (const float*)d_in[26];
    float* out = (float*)d_out;

    float *modp, *lnp, *qp, *kp, *vp, *yp, *hp;
    cudaGetSymbolAddress((void**)&modp, g_mod);
    cudaGetSymbolAddress((void**)&lnp,  g_ln);
    cudaGetSymbolAddress((void**)&qp,   g_q);
    cudaGetSymbolAddress((void**)&kp,   g_k);
    cudaGetSymbolAddress((void**)&vp,   g_v);
    cudaGetSymbolAddress((void**)&yp,   g_y);
    cudaGetSymbolAddress((void**)&hp,   g_h);

    int attn_smem = (4*64*ASTR)*sizeof(float) + 64*sizeof(int);
    cudaFuncSetAttribute(attn_k, cudaFuncAttributeMaxDynamicSharedMemorySize, attn_smem);

    dim3 gC(C_/128, R_/128);   // N=1024 GEMMs
    dim3 gM(M_/128, R_/128);   // N=4096 GEMM
    dim3 gA(T_/64, H_, B_);

    // x (residual stream) -> out
    copy_k<<<(R_*C_)/1024, 256>>>(x, out);
    // adaLN params
    mod_k<<<SIXC/256, 256>>>(c, w_ada, b_ada, modp);

    // ---- self attention ----
    ln_mod_k<<<R_, 256>>>(out, modp, 0, C_, lnp);
    sgemm_k<0><<<gC, 256>>>(lnp, wq, bq, qp, nullptr, C_, C_);
    sgemm_k<0><<<gC, 256>>>(lnp, wk, bk, kp, nullptr, C_, C_);
    sgemm_k<0><<<gC, 256>>>(lnp, wv, bv, vp, nullptr, C_, C_);
    attn_k<<<gA, 256, attn_smem>>>(qp, kp, vp, pmask, yp, T_);
    sgemm_k<2><<<gC, 256>>>(yp, wo, bo, out, modp + 2*C_, C_, C_);

    // ---- cross attention (reuses msa shift/scale/gate) ----
    ln_mod_k<<<R_, 256>>>(out, modp, 0, C_, lnp);
    sgemm_k<0><<<gC, 256>>>(lnp,   cwq, cbq, qp, nullptr, C_, C_);
    sgemm_k<0><<<gC, 256>>>(audio, cwk, cbk, kp, nullptr, C_, C_);
    sgemm_k<0><<<gC, 256>>>(audio, cwv, cbv, vp, nullptr, C_, C_);
    attn_k<<<gA, 256, attn_smem>>>(qp, kp, vp, amask, yp, TA_);
    sgemm_k<2><<<gC, 256>>>(yp, cwo, cbo, out, modp + 2*C_, C_, C_);

    // ---- MLP ----
    ln_mod_k<<<R_, 256>>>(out, modp, 3*C_, 4*C_, lnp);
    sgemm_k<1><<<gM, 256>>>(lnp, w1, b1, hp, nullptr, C_, M_);
    sgemm_k<2><<<gC, 256>>>(hp, w2, b2, out, modp + 5*C_, M_, C_);
}

// round 2
// speedup vs baseline: 1.4349x; 1.4349x over previous
#include <cuda_runtime.h>
#include <math.h>
#include <stdint.h>

#define T_  1024
#define B_  8
#define C_  1024
#define H_  16
#define D_  64
#define M_  4096
#define TA_ 1024
#define R_  (T_*B_)      // 8192 rows (t,b)
#define SIXC (6*C_)

// ---------------- scratch (device globals; no allocation allowed) -----------
__device__ float g_mod[B_*SIXC];          // adaLN params [B, 6C]
__device__ float g_ln [R_*C_];            // ln+modulate output
__device__ float g_q  [R_*C_];
__device__ float g_k  [R_*C_];
__device__ float g_v  [R_*C_];
__device__ float g_y  [R_*C_];            // attention output (pre-proj)
__device__ float g_h  [(size_t)R_*M_];    // mlp hidden (128 MB)

// ---------------- helpers ----------------------------------------------------
__device__ __forceinline__ float gelu_tanh(float x) {
    float x3 = x*x*x;
    return 0.5f*x*(1.f + tanhf(0.7978845608028654f*(x + 0.044715f*x3)));
}

__device__ __forceinline__ uint32_t f2tf(float f) {
    uint32_t r;
    asm("cvt.rna.tf32.f32 %0, %1;" : "=r"(r) : "f"(f));
    return r;
}

__device__ __forceinline__ void mma_tf32(float* d, const uint32_t* a, const uint32_t* b) {
    asm volatile(
        "mma.sync.aligned.m16n8k8.row.col.f32.tf32.tf32.f32 "
        "{%0,%1,%2,%3}, {%4,%5,%6,%7}, {%8,%9}, {%0,%1,%2,%3};\n"
        : "+f"(d[0]), "+f"(d[1]), "+f"(d[2]), "+f"(d[3])
        : "r"(a[0]), "r"(a[1]), "r"(a[2]), "r"(a[3]), "r"(b[0]), "r"(b[1]));
}

// ---------------- copy x -> out ----------------------------------------------
__global__ void copy_k(const float* __restrict__ in, float* __restrict__ out) {
    int i = blockIdx.x*blockDim.x + threadIdx.x;
    ((float4*)out)[i] = ((const float4*)in)[i];
}

// ---------------- mod = silu(c) @ w_ada + b_ada  [B,6C] ----------------------
__global__ void mod_k(const float* __restrict__ c, const float* __restrict__ w,
                      const float* __restrict__ bias, float* __restrict__ mod) {
    __shared__ float sc[B_][C_];
    int tid = threadIdx.x;
    for (int i = tid; i < B_*C_; i += 256) {
        float v = c[i];
        sc[i>>10][i&1023] = v / (1.f + __expf(-v));
    }
    __syncthreads();
    int col = blockIdx.x*256 + tid;
    float acc[B_];
    #pragma unroll
    for (int b = 0; b < B_; b++) acc[b] = 0.f;
    for (int k = 0; k < C_; k++) {
        float wv = w[(size_t)k*SIXC + col];
        #pragma unroll
        for (int b = 0; b < B_; b++) acc[b] += sc[b][k]*wv;
    }
    float bb = bias[col];
    #pragma unroll
    for (int b = 0; b < B_; b++) mod[b*SIXC + col] = acc[b] + bb;
}

// ---------------- LN (no affine) + modulate ----------------------------------
__global__ void ln_mod_k(const float* __restrict__ x, const float* __restrict__ mod,
                         int shiftOff, int scaleOff, float* __restrict__ out) {
    int row = blockIdx.x;
    int b   = row & (B_-1);
    const float* xr = x + (size_t)row*C_;
    float s = 0.f, s2 = 0.f;
    for (int i = threadIdx.x; i < C_; i += 256) {
        float v = xr[i]; s += v; s2 += v*v;
    }
    #pragma unroll
    for (int o = 16; o; o >>= 1) {
        s  += __shfl_xor_sync(0xffffffffu, s,  o);
        s2 += __shfl_xor_sync(0xffffffffu, s2, o);
    }
    __shared__ float red[2][8];
    int w = threadIdx.x >> 5, ln = threadIdx.x & 31;
    if (ln == 0) { red[0][w] = s; red[1][w] = s2; }
    __syncthreads();
    s = 0.f; s2 = 0.f;
    #pragma unroll
    for (int i = 0; i < 8; i++) { s += red[0][i]; s2 += red[1][i]; }
    float mu   = s * (1.f/C_);
    float var  = s2 * (1.f/C_) - mu*mu;
    float rstd = rsqrtf(var + 1e-6f);
    const float* sh = mod + b*SIXC + shiftOff;
    const float* sc = mod + b*SIXC + scaleOff;
    float* orow = out + (size_t)row*C_;
    for (int i = threadIdx.x; i < C_; i += 256)
        orow[i] = (xr[i]-mu)*rstd*(1.f+sc[i]) + sh[i];
}

// ---------------- tf32 tensor GEMM 128x128, BK=16, 256 thr -------------------
// out = A[R,K] @ W[K,N] (+ epilogue). EPI: 0 bias, 1 bias+gelu, 2 out += gate*(v+bias)
// As: [m][k] stride 20 (conflict-free frag LDS & STS.128)
// Bs: [k][n] stride 136 (conflict-free frag LDS & STS.128)
#define SA 20
#define SB 136
template<int EPI>
__global__ void __launch_bounds__(256, 2)
tgemm_k(const float* __restrict__ A, const float* __restrict__ W,
        const float* __restrict__ bias, float* __restrict__ out,
        const float* __restrict__ gate, int K, int N) {
    __shared__ uint32_t As[2][128*SA];
    __shared__ uint32_t Bs[2][16*SB];

    int tid  = threadIdx.x;
    int wid  = tid >> 5, lane = tid & 31;
    int g    = lane >> 2, tig = lane & 3;
    int wm   = wid >> 2, wn = wid & 3;          // warp tile 64x32: 2x4 warps
    int row0 = blockIdx.y*128, col0 = blockIdx.x*128;

    // A staging: thread -> rows (tid>>2) and (tid>>2)+64, float4 col (tid&3)
    int ar0 = tid >> 2, avv = tid & 3;
    const float* Ap0 = A + (size_t)(row0 + ar0     )*K + 4*avv;
    const float* Ap1 = A + (size_t)(row0 + ar0 + 64)*K + 4*avv;
    // B staging: thread -> k rows (tid>>5) and +8, float4 col (tid&31)
    int bk0 = tid >> 5, bvv = tid & 31;
    const float* Wp0 = W + (size_t)(bk0    )*N + col0 + 4*bvv;
    const float* Wp1 = W + (size_t)(bk0 + 8)*N + col0 + 4*bvv;

    float acc[4][4][4];
    #pragma unroll
    for (int i = 0; i < 4; i++)
        #pragma unroll
        for (int j = 0; j < 4; j++)
            #pragma unroll
            for (int q = 0; q < 4; q++) acc[i][j][q] = 0.f;

    float4 a0g = *(const float4*)Ap0;
    float4 a1g = *(const float4*)Ap1;
    float4 b0g = *(const float4*)Wp0;
    float4 b1g = *(const float4*)Wp1;

    // store chunk 0 into buffer 0
    {
        uint32_t* d0 = &As[0][ ar0      *SA + 4*avv];
        d0[0]=f2tf(a0g.x); d0[1]=f2tf(a0g.y); d0[2]=f2tf(a0g.z); d0[3]=f2tf(a0g.w);
        uint32_t* d1 = &As[0][(ar0 + 64)*SA + 4*avv];
        d1[0]=f2tf(a1g.x); d1[1]=f2tf(a1g.y); d1[2]=f2tf(a1g.z); d1[3]=f2tf(a1g.w);
        uint32_t* e0 = &Bs[0][ bk0     *SB + 4*bvv];
        e0[0]=f2tf(b0g.x); e0[1]=f2tf(b0g.y); e0[2]=f2tf(b0g.z); e0[3]=f2tf(b0g.w);
        uint32_t* e1 = &Bs[0][(bk0 + 8)*SB + 4*bvv];
        e1[0]=f2tf(b1g.x); e1[1]=f2tf(b1g.y); e1[2]=f2tf(b1g.z); e1[3]=f2tf(b1g.w);
    }
    __syncthreads();

    int buf = 0;
    int nchunk = K >> 4;
    for (int ch = 0; ch < nchunk; ch++) {
        bool more = (ch + 1 < nchunk);
        if (more) {
            Ap0 += 16; Ap1 += 16;
            Wp0 += (size_t)16*N; Wp1 += (size_t)16*N;
            a0g = *(const float4*)Ap0;
            a1g = *(const float4*)Ap1;
            b0g = *(const float4*)Wp0;
            b1g = *(const float4*)Wp1;
        }

        #pragma unroll
        for (int ks = 0; ks < 16; ks += 8) {
            uint32_t af[4][4], bf[4][2];
            #pragma unroll
            for (int mt = 0; mt < 4; mt++) {
                int m0 = wm*64 + mt*16;
                const uint32_t* p = &As[buf][(m0 + g)*SA + ks + tig];
                af[mt][0] = p[0];
                af[mt][2] = p[4];
                af[mt][1] = p[8*SA];
                af[mt][3] = p[8*SA + 4];
            }
            #pragma unroll
            for (int nt = 0; nt < 4; nt++) {
                int n0 = wn*32 + nt*8 + g;
                bf[nt][0] = Bs[buf][(ks + tig    )*SB + n0];
                bf[nt][1] = Bs[buf][(ks + tig + 4)*SB + n0];
            }
            #pragma unroll
            for (int mt = 0; mt < 4; mt++)
                #pragma unroll
                for (int nt = 0; nt < 4; nt++)
                    mma_tf32(acc[mt][nt], af[mt], bf[nt]);
        }

        if (more) {
            int nb = buf ^ 1;
            uint32_t* d0 = &As[nb][ ar0      *SA + 4*avv];
            d0[0]=f2tf(a0g.x); d0[1]=f2tf(a0g.y); d0[2]=f2tf(a0g.z); d0[3]=f2tf(a0g.w);
            uint32_t* d1 = &As[nb][(ar0 + 64)*SA + 4*avv];
            d1[0]=f2tf(a1g.x); d1[1]=f2tf(a1g.y); d1[2]=f2tf(a1g.z); d1[3]=f2tf(a1g.w);
            uint32_t* e0 = &Bs[nb][ bk0     *SB + 4*bvv];
            e0[0]=f2tf(b0g.x); e0[1]=f2tf(b0g.y); e0[2]=f2tf(b0g.z); e0[3]=f2tf(b0g.w);
            uint32_t* e1 = &Bs[nb][(bk0 + 8)*SB + 4*bvv];
            e1[0]=f2tf(b1g.x); e1[1]=f2tf(b1g.y); e1[2]=f2tf(b1g.z); e1[3]=f2tf(b1g.w);
        }
        __syncthreads();
        buf ^= 1;
    }

    // epilogue: d0,d1 -> row g, cols 2tig,2tig+1 ; d2,d3 -> row g+8
    #pragma unroll
    for (int mt = 0; mt < 4; mt++) {
        int rbase = row0 + wm*64 + mt*16 + g;
        #pragma unroll
        for (int half = 0; half < 2; half++) {
            int rr = rbase + 8*half;
            int bb = rr & (B_-1);
            float* orow = out + (size_t)rr*N;
            #pragma unroll
            for (int nt = 0; nt < 4; nt++) {
                int cb = col0 + wn*32 + nt*8 + 2*tig;
                float v0 = acc[mt][nt][2*half + 0] + bias[cb];
                float v1 = acc[mt][nt][2*half + 1] + bias[cb+1];
                if (EPI == 0) {
                    orow[cb]   = v0;
                    orow[cb+1] = v1;
                } else if (EPI == 1) {
                    orow[cb]   = gelu_tanh(v0);
                    orow[cb+1] = gelu_tanh(v1);
                } else {
                    orow[cb]   += gate[bb*SIXC + cb  ]*v0;
                    orow[cb+1] += gate[bb*SIXC + cb+1]*v1;
                }
            }
        }
    }
}

// ---------------- flash attention (fp32, unchanged) --------------------------
#define ASTR 65
__global__ void attn_k(const float* __restrict__ Q, const float* __restrict__ Kx,
                       const float* __restrict__ Vx, const int* __restrict__ mask,
                       float* __restrict__ Y, int Tk) {
    extern __shared__ float sm[];
    float* Qs = sm;
    float* Ks = Qs + 64*ASTR;
    float* Vs = Ks + 64*ASTR;
    float* Ss = Vs + 64*ASTR;
    int*   Ms = (int*)(Ss + 64*ASTR);

    int tid = threadIdx.x;
    int q0 = blockIdx.x*64, h = blockIdx.y, b = blockIdx.z;
    size_t hoff = (size_t)h*D_;

    for (int i = tid; i < 64*64; i += 256) {
        int r = i >> 6, d = i & 63;
        Qs[r*ASTR + d] = Q[((size_t)(q0+r)*B_ + b)*C_ + hoff + d];
    }
    int r = tid >> 2, g = tid & 3, c0 = g*16;
    float m = -1e30f, l = 0.f;
    float acc[16];
    #pragma unroll
    for (int i = 0; i < 16; i++) acc[i] = 0.f;
    __syncthreads();

    for (int k0 = 0; k0 < Tk; k0 += 64) {
        for (int i = tid; i < 64*64; i += 256) {
            int rr = i >> 6, d = i & 63;
            size_t gi = ((size_t)(k0+rr)*B_ + b)*C_ + hoff + d;
            Ks[rr*ASTR + d] = Kx[gi];
            Vs[rr*ASTR + d] = Vx[gi];
        }
        if (tid < 64) Ms[tid] = mask[(size_t)b*Tk + k0 + tid];
        __syncthreads();

        float sv[16];
        #pragma unroll
        for (int j = 0; j < 16; j++) sv[j] = 0.f;
        #pragma unroll 8
        for (int kk = 0; kk < 64; kk++) {
            float qv = Qs[r*ASTR + kk];
            #pragma unroll
            for (int j = 0; j < 16; j++) sv[j] += qv*Ks[(c0+j)*ASTR + kk];
        }
        #pragma unroll
        for (int j = 0; j < 16; j++)
            Ss[r*ASTR + c0 + j] = Ms[c0+j] ? -1e30f : sv[j]*0.125f;
        __syncthreads();

        float mnew = m;
        #pragma unroll 8
        for (int j = 0; j < 64; j++) mnew = fmaxf(mnew, Ss[r*ASTR + j]);
        float scale = __expf(m - mnew);
        m = mnew;
        __syncthreads();

        #pragma unroll
        for (int j = 0; j < 16; j++) {
            float s = Ss[r*ASTR + c0 + j];
            Ss[r*ASTR + c0 + j] = (s > -1e29f) ? __expf(s - mnew) : 0.f;
        }
        __syncthreads();

        l *= scale;
        #pragma unroll
        for (int i = 0; i < 16; i++) acc[i] *= scale;
        float rs = 0.f;
        #pragma unroll 4
        for (int j = 0; j < 64; j++) {
            float p = Ss[r*ASTR + j];
            rs += p;
            #pragma unroll
            for (int cc = 0; cc < 16; cc++) acc[cc] += p*Vs[j*ASTR + c0 + cc];
        }
        l += rs;
        __syncthreads();
    }
    float inv = 1.f/l;
    size_t obase = ((size_t)(q0+r)*B_ + b)*C_ + hoff + c0;
    #pragma unroll
    for (int cc = 0; cc < 16; cc++) Y[obase + cc] = acc[cc]*inv;
}

// ---------------- launch -----------------------------------------------------
extern "C" void kernel_launch(void* const* d_in, const int* in_sizes, int n_in,
                              void* d_out, int out_size) {
    const float* x     = (const float*)d_in[0];
    const float* c     = (const float*)d_in[1];
    const int*   pmask = (const int*)  d_in[2];
    const float* audio = (const float*)d_in[3];
    const int*   amask = (const int*)  d_in[4];
    const float* w_ada = (const float*)d_in[5];
    const float* b_ada = (const float*)d_in[6];
    const float* wq = (const float*)d_in[7];   const float* bq = (const float*)d_in[8];
    const float* wk = (const float*)d_in[9];   const float* bk = (const float*)d_in[10];
    const float* wv = (const float*)d_in[11];  const float* bv = (const float*)d_in[12];
    const float* wo = (const float*)d_in[13];  const float* bo = (const float*)d_in[14];
    const float* cwq = (const float*)d_in[15]; const float* cbq = (const float*)d_in[16];
    const float* cwk = (const float*)d_in[17]; const float* cbk = (const float*)d_in[18];
    const float* cwv = (const float*)d_in[19]; const float* cbv = (const float*)d_in[20];
    const float* cwo = (const float*)d_in[21]; const float* cbo = (const float*)d_in[22];
    const float* w1 = (const float*)d_in[23];  const float* b1 = (const float*)d_in[24];
    const float* w2 = (const float*)d_in[25];  const float* b2 = (const float*)d_in[26];
    float* out = (float*)d_out;

    float *modp, *lnp, *qp, *kp, *vp, *yp, *hp;
    cudaGetSymbolAddress((void**)&modp, g_mod);
    cudaGetSymbolAddress((void**)&lnp,  g_ln);
    cudaGetSymbolAddress((void**)&qp,   g_q);
    cudaGetSymbolAddress((void**)&kp,   g_k);
    cudaGetSymbolAddress((void**)&vp,   g_v);
    cudaGetSymbolAddress((void**)&yp,   g_y);
    cudaGetSymbolAddress((void**)&hp,   g_h);

    int attn_smem = (4*64*ASTR)*sizeof(float) + 64*sizeof(int);
    cudaFuncSetAttribute(attn_k, cudaFuncAttributeMaxDynamicSharedMemorySize, attn_smem);

    dim3 gC(C_/128, R_/128);   // N=1024 GEMMs
    dim3 gM(M_/128, R_/128);   // N=4096 GEMM
    dim3 gA(T_/64, H_, B_);

    copy_k<<<(R_*C_)/1024, 256>>>(x, out);
    mod_k<<<SIXC/256, 256>>>(c, w_ada, b_ada, modp);

    // ---- self attention ----
    ln_mod_k<<<R_, 256>>>(out, modp, 0, C_, lnp);
    tgemm_k<0><<<gC, 256>>>(lnp, wq, bq, qp, nullptr, C_, C_);
    tgemm_k<0><<<gC, 256>>>(lnp, wk, bk, kp, nullptr, C_, C_);
    tgemm_k<0><<<gC, 256>>>(lnp, wv, bv, vp, nullptr, C_, C_);
    attn_k<<<gA, 256, attn_smem>>>(qp, kp, vp, pmask, yp, T_);
    tgemm_k<2><<<gC, 256>>>(yp, wo, bo, out, modp + 2*C_, C_, C_);

    // ---- cross attention (reuses msa shift/scale/gate) ----
    ln_mod_k<<<R_, 256>>>(out, modp, 0, C_, lnp);
    tgemm_k<0><<<gC, 256>>>(lnp,   cwq, cbq, qp, nullptr, C_, C_);
    tgemm_k<0><<<gC, 256>>>(audio, cwk, cbk, kp, nullptr, C_, C_);
    tgemm_k<0><<<gC, 256>>>(audio, cwv, cbv, vp, nullptr, C_, C_);
    attn_k<<<gA, 256, attn_smem>>>(qp, kp, vp, amask, yp, TA_);
    tgemm_k<2><<<gC, 256>>>(yp, cwo, cbo, out, modp + 2*C_, C_, C_);

    // ---- MLP ----
    ln_mod_k<<<R_, 256>>>(out, modp, 3*C_, 4*C_, lnp);
    tgemm_k<1><<<gM, 256>>>(lnp, w1, b1, hp, nullptr, C_, M_);
    tgemm_k<2><<<gC, 256>>>(hp, w2, b2, out, modp + 5*C_, M_, C_);
}

// round 3
// speedup vs baseline: 4.5144x; 3.1462x over previous
#include <cuda_runtime.h>
#include <math.h>
#include <stdint.h>

#define T_  1024
#define B_  8
#define C_  1024
#define H_  16
#define D_  64
#define M_  4096
#define TA_ 1024
#define R_  (T_*B_)      // 8192 rows (t,b)
#define SIXC (6*C_)

// ---------------- scratch (device globals; no allocation allowed) -----------
__device__ float g_mod[B_*SIXC];
__device__ float g_ln [R_*C_];
__device__ float g_q  [R_*C_];
__device__ float g_k  [R_*C_];
__device__ float g_v  [R_*C_];
__device__ float g_y  [R_*C_];
__device__ float g_h  [(size_t)R_*M_];

// ---------------- helpers ----------------------------------------------------
__device__ __forceinline__ float gelu_tanh(float x) {
    float x3 = x*x*x;
    return 0.5f*x*(1.f + tanhf(0.7978845608028654f*(x + 0.044715f*x3)));
}

__device__ __forceinline__ uint32_t f2tf(float f) {
    uint32_t r;
    asm("cvt.rna.tf32.f32 %0, %1;" : "=r"(r) : "f"(f));
    return r;
}

__device__ __forceinline__ void mma_tf32(float* d, const uint32_t* a, const uint32_t* b) {
    asm volatile(
        "mma.sync.aligned.m16n8k8.row.col.f32.tf32.tf32.f32 "
        "{%0,%1,%2,%3}, {%4,%5,%6,%7}, {%8,%9}, {%0,%1,%2,%3};\n"
        : "+f"(d[0]), "+f"(d[1]), "+f"(d[2]), "+f"(d[3])
        : "r"(a[0]), "r"(a[1]), "r"(a[2]), "r"(a[3]), "r"(b[0]), "r"(b[1]));
}

// ---------------- copy x -> out ----------------------------------------------
__global__ void copy_k(const float* __restrict__ in, float* __restrict__ out) {
    int i = blockIdx.x*blockDim.x + threadIdx.x;
    ((float4*)out)[i] = ((const float4*)in)[i];
}

// ---------------- mod = silu(c) @ w_ada + b_ada  [B,6C] ----------------------
__global__ void mod_k(const float* __restrict__ c, const float* __restrict__ w,
                      const float* __restrict__ bias, float* __restrict__ mod) {
    __shared__ float sc[B_][C_];
    int tid = threadIdx.x;
    for (int i = tid; i < B_*C_; i += 256) {
        float v = c[i];
        sc[i>>10][i&1023] = v / (1.f + __expf(-v));
    }
    __syncthreads();
    int col = blockIdx.x*256 + tid;
    float acc[B_];
    #pragma unroll
    for (int b = 0; b < B_; b++) acc[b] = 0.f;
    for (int k = 0; k < C_; k++) {
        float wv = w[(size_t)k*SIXC + col];
        #pragma unroll
        for (int b = 0; b < B_; b++) acc[b] += sc[b][k]*wv;
    }
    float bb = bias[col];
    #pragma unroll
    for (int b = 0; b < B_; b++) mod[b*SIXC + col] = acc[b] + bb;
}

// ---------------- LN (no affine) + modulate ----------------------------------
__global__ void ln_mod_k(const float* __restrict__ x, const float* __restrict__ mod,
                         int shiftOff, int scaleOff, float* __restrict__ out) {
    int row = blockIdx.x;
    int b   = row & (B_-1);
    const float* xr = x + (size_t)row*C_;
    float s = 0.f, s2 = 0.f;
    for (int i = threadIdx.x; i < C_; i += 256) {
        float v = xr[i]; s += v; s2 += v*v;
    }
    #pragma unroll
    for (int o = 16; o; o >>= 1) {
        s  += __shfl_xor_sync(0xffffffffu, s,  o);
        s2 += __shfl_xor_sync(0xffffffffu, s2, o);
    }
    __shared__ float red[2][8];
    int w = threadIdx.x >> 5, ln = threadIdx.x & 31;
    if (ln == 0) { red[0][w] = s; red[1][w] = s2; }
    __syncthreads();
    s = 0.f; s2 = 0.f;
    #pragma unroll
    for (int i = 0; i < 8; i++) { s += red[0][i]; s2 += red[1][i]; }
    float mu   = s * (1.f/C_);
    float var  = s2 * (1.f/C_) - mu*mu;
    float rstd = rsqrtf(var + 1e-6f);
    const float* sh = mod + b*SIXC + shiftOff;
    const float* sc = mod + b*SIXC + scaleOff;
    float* orow = out + (size_t)row*C_;
    for (int i = threadIdx.x; i < C_; i += 256)
        orow[i] = (xr[i]-mu)*rstd*(1.f+sc[i]) + sh[i];
}

// ---------------- tf32 tensor GEMM 128x128, BK=16, 256 thr -------------------
#define SA 20
#define SB 136
template<int EPI>
__global__ void __launch_bounds__(256, 2)
tgemm_k(const float* __restrict__ A, const float* __restrict__ W,
        const float* __restrict__ bias, float* __restrict__ out,
        const float* __restrict__ gate, int K, int N) {
    __shared__ uint32_t As[2][128*SA];
    __shared__ uint32_t Bs[2][16*SB];

    int tid  = threadIdx.x;
    int wid  = tid >> 5, lane = tid & 31;
    int g    = lane >> 2, tig = lane & 3;
    int wm   = wid >> 2, wn = wid & 3;
    int row0 = blockIdx.y*128, col0 = blockIdx.x*128;

    int ar0 = tid >> 2, avv = tid & 3;
    const float* Ap0 = A + (size_t)(row0 + ar0     )*K + 4*avv;
    const float* Ap1 = A + (size_t)(row0 + ar0 + 64)*K + 4*avv;
    int bk0 = tid >> 5, bvv = tid & 31;
    const float* Wp0 = W + (size_t)(bk0    )*N + col0 + 4*bvv;
    const float* Wp1 = W + (size_t)(bk0 + 8)*N + col0 + 4*bvv;

    float acc[4][4][4];
    #pragma unroll
    for (int i = 0; i < 4; i++)
        #pragma unroll
        for (int j = 0; j < 4; j++)
            #pragma unroll
            for (int q = 0; q < 4; q++) acc[i][j][q] = 0.f;

    float4 a0g = *(const float4*)Ap0;
    float4 a1g = *(const float4*)Ap1;
    float4 b0g = *(const float4*)Wp0;
    float4 b1g = *(const float4*)Wp1;

    {
        uint32_t* d0 = &As[0][ ar0      *SA + 4*avv];
        d0[0]=f2tf(a0g.x); d0[1]=f2tf(a0g.y); d0[2]=f2tf(a0g.z); d0[3]=f2tf(a0g.w);
        uint32_t* d1 = &As[0][(ar0 + 64)*SA + 4*avv];
        d1[0]=f2tf(a1g.x); d1[1]=f2tf(a1g.y); d1[2]=f2tf(a1g.z); d1[3]=f2tf(a1g.w);
        uint32_t* e0 = &Bs[0][ bk0     *SB + 4*bvv];
        e0[0]=f2tf(b0g.x); e0[1]=f2tf(b0g.y); e0[2]=f2tf(b0g.z); e0[3]=f2tf(b0g.w);
        uint32_t* e1 = &Bs[0][(bk0 + 8)*SB + 4*bvv];
        e1[0]=f2tf(b1g.x); e1[1]=f2tf(b1g.y); e1[2]=f2tf(b1g.z); e1[3]=f2tf(b1g.w);
    }
    __syncthreads();

    int buf = 0;
    int nchunk = K >> 4;
    for (int ch = 0; ch < nchunk; ch++) {
        bool more = (ch + 1 < nchunk);
        if (more) {
            Ap0 += 16; Ap1 += 16;
            Wp0 += (size_t)16*N; Wp1 += (size_t)16*N;
            a0g = *(const float4*)Ap0;
            a1g = *(const float4*)Ap1;
            b0g = *(const float4*)Wp0;
            b1g = *(const float4*)Wp1;
        }

        #pragma unroll
        for (int ks = 0; ks < 16; ks += 8) {
            uint32_t af[4][4], bf[4][2];
            #pragma unroll
            for (int mt = 0; mt < 4; mt++) {
                int m0 = wm*64 + mt*16;
                const uint32_t* p = &As[buf][(m0 + g)*SA + ks + tig];
                af[mt][0] = p[0];
                af[mt][2] = p[4];
                af[mt][1] = p[8*SA];
                af[mt][3] = p[8*SA + 4];
            }
            #pragma unroll
            for (int nt = 0; nt < 4; nt++) {
                int n0 = wn*32 + nt*8 + g;
                bf[nt][0] = Bs[buf][(ks + tig    )*SB + n0];
                bf[nt][1] = Bs[buf][(ks + tig + 4)*SB + n0];
            }
            #pragma unroll
            for (int mt = 0; mt < 4; mt++)
                #pragma unroll
                for (int nt = 0; nt < 4; nt++)
                    mma_tf32(acc[mt][nt], af[mt], bf[nt]);
        }

        if (more) {
            int nb = buf ^ 1;
            uint32_t* d0 = &As[nb][ ar0      *SA + 4*avv];
            d0[0]=f2tf(a0g.x); d0[1]=f2tf(a0g.y); d0[2]=f2tf(a0g.z); d0[3]=f2tf(a0g.w);
            uint32_t* d1 = &As[nb][(ar0 + 64)*SA + 4*avv];
            d1[0]=f2tf(a1g.x); d1[1]=f2tf(a1g.y); d1[2]=f2tf(a1g.z); d1[3]=f2tf(a1g.w);
            uint32_t* e0 = &Bs[nb][ bk0     *SB + 4*bvv];
            e0[0]=f2tf(b0g.x); e0[1]=f2tf(b0g.y); e0[2]=f2tf(b0g.z); e0[3]=f2tf(b0g.w);
            uint32_t* e1 = &Bs[nb][(bk0 + 8)*SB + 4*bvv];
            e1[0]=f2tf(b1g.x); e1[1]=f2tf(b1g.y); e1[2]=f2tf(b1g.z); e1[3]=f2tf(b1g.w);
        }
        __syncthreads();
        buf ^= 1;
    }

    #pragma unroll
    for (int mt = 0; mt < 4; mt++) {
        int rbase = row0 + wm*64 + mt*16 + g;
        #pragma unroll
        for (int half = 0; half < 2; half++) {
            int rr = rbase + 8*half;
            int bb = rr & (B_-1);
            float* orow = out + (size_t)rr*N;
            #pragma unroll
            for (int nt = 0; nt < 4; nt++) {
                int cb = col0 + wn*32 + nt*8 + 2*tig;
                float v0 = acc[mt][nt][2*half + 0] + bias[cb];
                float v1 = acc[mt][nt][2*half + 1] + bias[cb+1];
                if (EPI == 0) {
                    orow[cb]   = v0;
                    orow[cb+1] = v1;
                } else if (EPI == 1) {
                    orow[cb]   = gelu_tanh(v0);
                    orow[cb+1] = gelu_tanh(v1);
                } else {
                    orow[cb]   += gate[bb*SIXC + cb  ]*v0;
                    orow[cb+1] += gate[bb*SIXC + cb+1]*v1;
                }
            }
        }
    }
}

// ---------------- tf32 tensor-core flash attention ---------------------------
// grid (T/64, H, B), 256 thr (8 warps: wm=wid>>1 row-tile, wn=wid&1 col-half).
// Qs/Ks/Ss stride 68 (conflict-free frag LDS), Vs stride 72.
#define AQS 68
#define AVS 72
__global__ void __launch_bounds__(256, 2)
fattn_k(const float* __restrict__ Q, const float* __restrict__ Kx,
        const float* __restrict__ Vx, const int* __restrict__ mask,
        float* __restrict__ Y, int Tk) {
    extern __shared__ uint32_t smu[];
    uint32_t* Qs = smu;
    uint32_t* Ks = Qs + 64*AQS;
    uint32_t* Vs = Ks + 64*AQS;
    uint32_t* Ss = Vs + 64*AVS;
    float*    Ssf  = (float*)Ss;
    float*    mrow = (float*)(Ss + 64*AQS);
    float*    lrow = mrow + 64;
    float*    srow = lrow + 64;
    int*      Ms   = (int*)(srow + 64);

    int tid  = threadIdx.x;
    int lane = tid & 31, wid = tid >> 5;
    int g    = lane >> 2, tig = lane & 3;
    int wm   = wid >> 1, wn = wid & 1;
    int q0 = blockIdx.x*64, h = blockIdx.y, b = blockIdx.z;
    size_t hoff = (size_t)h*D_;

    // load Q tile (tf32)
    #pragma unroll
    for (int p = 0; p < 4; p++) {
        int idx = tid + p*256;
        int r = idx >> 4, c4 = (idx & 15)*4;
        float4 v = *(const float4*)&Q[((size_t)(q0+r)*B_ + b)*C_ + hoff + c4];
        uint32_t* d = &Qs[r*AQS + c4];
        d[0]=f2tf(v.x); d[1]=f2tf(v.y); d[2]=f2tf(v.z); d[3]=f2tf(v.w);
    }
    if (tid < 64) { mrow[tid] = -1e30f; lrow[tid] = 0.f; }

    float oacc[4][4];
    #pragma unroll
    for (int i = 0; i < 4; i++)
        #pragma unroll
        for (int j = 0; j < 4; j++) oacc[i][j] = 0.f;
    __syncthreads();

    for (int k0 = 0; k0 < Tk; k0 += 64) {
        // load K,V tiles
        #pragma unroll
        for (int p = 0; p < 4; p++) {
            int idx = tid + p*256;
            int r = idx >> 4, c4 = (idx & 15)*4;
            size_t gi = ((size_t)(k0+r)*B_ + b)*C_ + hoff + c4;
            float4 kv = *(const float4*)&Kx[gi];
            float4 vv = *(const float4*)&Vx[gi];
            uint32_t* dk = &Ks[r*AQS + c4];
            dk[0]=f2tf(kv.x); dk[1]=f2tf(kv.y); dk[2]=f2tf(kv.z); dk[3]=f2tf(kv.w);
            uint32_t* dv = &Vs[r*AVS + c4];
            dv[0]=f2tf(vv.x); dv[1]=f2tf(vv.y); dv[2]=f2tf(vv.z); dv[3]=f2tf(vv.w);
        }
        if (tid < 64) Ms[tid] = mask[(size_t)b*Tk + k0 + tid];
        __syncthreads();

        // ---- S = Q K^T (warp: rows wm*16..+15, cols wn*32..+31) ----
        float sacc[4][4];
        #pragma unroll
        for (int i = 0; i < 4; i++)
            #pragma unroll
            for (int j = 0; j < 4; j++) sacc[i][j] = 0.f;
        #pragma unroll
        for (int ks = 0; ks < 64; ks += 8) {
            uint32_t af[4];
            const uint32_t* qp = &Qs[(wm*16 + g)*AQS + ks + tig];
            af[0] = qp[0]; af[1] = qp[8*AQS]; af[2] = qp[4]; af[3] = qp[8*AQS + 4];
            #pragma unroll
            for (int nt = 0; nt < 4; nt++) {
                int n0 = wn*32 + nt*8;
                uint32_t bf[2];
                bf[0] = Ks[(n0 + g)*AQS + ks + tig];
                bf[1] = Ks[(n0 + g)*AQS + ks + tig + 4];
                mma_tf32(sacc[nt], af, bf);
            }
        }
        #pragma unroll
        for (int nt = 0; nt < 4; nt++) {
            int cc = wn*32 + nt*8 + 2*tig;
            int r0 = wm*16 + g;
            *(float2*)&Ssf[ r0     *AQS + cc] = make_float2(sacc[nt][0], sacc[nt][1]);
            *(float2*)&Ssf[(r0 + 8)*AQS + cc] = make_float2(sacc[nt][2], sacc[nt][3]);
        }
        __syncthreads();

        // ---- online softmax (thread: row tid>>2, 16 cols) ----
        {
            int r  = tid >> 2, c0 = (tid & 3)*16;
            float s[16];
            #pragma unroll
            for (int j = 0; j < 16; j++)
                s[j] = Ms[c0 + j] ? -1e30f : Ssf[r*AQS + c0 + j]*0.125f;
            float mx = s[0];
            #pragma unroll
            for (int j = 1; j < 16; j++) mx = fmaxf(mx, s[j]);
            mx = fmaxf(mx, __shfl_xor_sync(0xffffffffu, mx, 1));
            mx = fmaxf(mx, __shfl_xor_sync(0xffffffffu, mx, 2));
            float mold = mrow[r];
            float mnew = fmaxf(mold, mx);
            float rs = 0.f;
            #pragma unroll
            for (int j = 0; j < 16; j++) {
                float p = (s[j] > -1e29f) ? __expf(s[j] - mnew) : 0.f;
                rs += p;
                Ss[r*AQS + c0 + j] = f2tf(p);
            }
            rs += __shfl_xor_sync(0xffffffffu, rs, 1);
            rs += __shfl_xor_sync(0xffffffffu, rs, 2);
            if ((tid & 3) == 0) {
                float scl = __expf(mold - mnew);
                lrow[r] = lrow[r]*scl + rs;
                mrow[r] = mnew;
                srow[r] = scl;
            }
        }
        __syncthreads();

        // ---- O = O*scale + P @ V ----
        float s0 = srow[wm*16 + g];
        float s1 = srow[wm*16 + g + 8];
        #pragma unroll
        for (int nt = 0; nt < 4; nt++) {
            oacc[nt][0] *= s0; oacc[nt][1] *= s0;
            oacc[nt][2] *= s1; oacc[nt][3] *= s1;
        }
        #pragma unroll
        for (int ks = 0; ks < 64; ks += 8) {
            uint32_t af[4];
            const uint32_t* pp = &Ss[(wm*16 + g)*AQS + ks + tig];
            af[0] = pp[0]; af[1] = pp[8*AQS]; af[2] = pp[4]; af[3] = pp[8*AQS + 4];
            #pragma unroll
            for (int nt = 0; nt < 4; nt++) {
                int n0 = wn*32 + nt*8;
                uint32_t bf[2];
                bf[0] = Vs[(ks + tig    )*AVS + n0 + g];
                bf[1] = Vs[(ks + tig + 4)*AVS + n0 + g];
                mma_tf32(oacc[nt], af, bf);
            }
        }
        __syncthreads();
    }

    // epilogue: O / l
    float inv0 = 1.f / lrow[wm*16 + g];
    float inv1 = 1.f / lrow[wm*16 + g + 8];
    int r0 = q0 + wm*16 + g;
    #pragma unroll
    for (int nt = 0; nt < 4; nt++) {
        int dd = wn*32 + nt*8 + 2*tig;
        *(float2*)&Y[((size_t) r0     *B_ + b)*C_ + hoff + dd] =
            make_float2(oacc[nt][0]*inv0, oacc[nt][1]*inv0);
        *(float2*)&Y[((size_t)(r0 + 8)*B_ + b)*C_ + hoff + dd] =
            make_float2(oacc[nt][2]*inv1, oacc[nt][3]*inv1);
    }
}

// ---------------- launch -----------------------------------------------------
extern "C" void kernel_launch(void* const* d_in, const int* in_sizes, int n_in,
                              void* d_out, int out_size) {
    const float* x     = (const float*)d_in[0];
    const float* c     = (const float*)d_in[1];
    const int*   pmask = (const int*)  d_in[2];
    const float* audio = (const float*)d_in[3];
    const int*   amask = (const int*)  d_in[4];
    const float* w_ada = (const float*)d_in[5];
    const float* b_ada = (const float*)d_in[6];
    const float* wq = (const float*)d_in[7];   const float* bq = (const float*)d_in[8];
    const float* wk = (const float*)d_in[9];   const float* bk = (const float*)d_in[10];
    const float* wv = (const float*)d_in[11];  const float* bv = (const float*)d_in[12];
    const float* wo = (const float*)d_in[13];  const float* bo = (const float*)d_in[14];
    const float* cwq = (const float*)d_in[15]; const float* cbq = (const float*)d_in[16];
    const float* cwk = (const float*)d_in[17]; const float* cbk = (const float*)d_in[18];
    const float* cwv = (const float*)d_in[19]; const float* cbv = (const float*)d_in[20];
    const float* cwo = (const float*)d_in[21]; const float* cbo = (const float*)d_in[22];
    const float* w1 = (const float*)d_in[23];  const float* b1 = (const float*)d_in[24];
    const float* w2 = (const float*)d_in[25];  const float* b2 = (const float*)d_in[26];
    float* out = (float*)d_out;

    float *modp, *lnp, *qp, *kp, *vp, *yp, *hp;
    cudaGetSymbolAddress((void**)&modp, g_mod);
    cudaGetSymbolAddress((void**)&lnp,  g_ln);
    cudaGetSymbolAddress((void**)&qp,   g_q);
    cudaGetSymbolAddress((void**)&kp,   g_k);
    cudaGetSymbolAddress((void**)&vp,   g_v);
    cudaGetSymbolAddress((void**)&yp,   g_y);
    cudaGetSymbolAddress((void**)&hp,   g_h);

    int attn_smem = (3*64*AQS + 64*AVS + 3*64)*sizeof(uint32_t) + 64*sizeof(int);
    cudaFuncSetAttribute(fattn_k, cudaFuncAttributeMaxDynamicSharedMemorySize, attn_smem);

    dim3 gC(C_/128, R_/128);
    dim3 gM(M_/128, R_/128);
    dim3 gA(T_/64, H_, B_);

    copy_k<<<(R_*C_)/1024, 256>>>(x, out);
    mod_k<<<SIXC/256, 256>>>(c, w_ada, b_ada, modp);

    // ---- self attention ----
    ln_mod_k<<<R_, 256>>>(out, modp, 0, C_, lnp);
    tgemm_k<0><<<gC, 256>>>(lnp, wq, bq, qp, nullptr, C_, C_);
    tgemm_k<0><<<gC, 256>>>(lnp, wk, bk, kp, nullptr, C_, C_);
    tgemm_k<0><<<gC, 256>>>(lnp, wv, bv, vp, nullptr, C_, C_);
    fattn_k<<<gA, 256, attn_smem>>>(qp, kp, vp, pmask, yp, T_);
    tgemm_k<2><<<gC, 256>>>(yp, wo, bo, out, modp + 2*C_, C_, C_);

    // ---- cross attention (reuses msa shift/scale/gate) ----
    ln_mod_k<<<R_, 256>>>(out, modp, 0, C_, lnp);
    tgemm_k<0><<<gC, 256>>>(lnp,   cwq, cbq, qp, nullptr, C_, C_);
    tgemm_k<0><<<gC, 256>>>(audio, cwk, cbk, kp, nullptr, C_, C_);
    tgemm_k<0><<<gC, 256>>>(audio, cwv, cbv, vp, nullptr, C_, C_);
    fattn_k<<<gA, 256, attn_smem>>>(qp, kp, vp, amask, yp, TA_);
    tgemm_k<2><<<gC, 256>>>(yp, cwo, cbo, out, modp + 2*C_, C_, C_);

    // ---- MLP ----
    ln_mod_k<<<R_, 256>>>(out, modp, 3*C_, 4*C_, lnp);
    tgemm_k<1><<<gM, 256>>>(lnp, w1, b1, hp, nullptr, C_, M_);
    tgemm_k<2><<<gC, 256>>>(hp, w2, b2, out, modp + 5*C_, M_, C_);
}

// round 4
// speedup vs baseline: 4.5287x; 1.0032x over previous
#include <cuda_runtime.h>
#include <math.h>
#include <stdint.h>

#define T_  1024
#define B_  8
#define C_  1024
#define H_  16
#define D_  64
#define M_  4096
#define TA_ 1024
#define R_  (T_*B_)      // 8192 rows (t,b)
#define SIXC (6*C_)

// ---------------- scratch (device globals; no allocation allowed) -----------
__device__ float g_mod[B_*SIXC];
__device__ float g_ln [R_*C_];
__device__ float g_q  [R_*C_];
__device__ float g_k  [R_*C_];
__device__ float g_v  [R_*C_];
__device__ float g_y  [R_*C_];
__device__ float g_h  [(size_t)R_*M_];

// ---------------- helpers ----------------------------------------------------
__device__ __forceinline__ float gelu_tanh(float x) {
    float x3 = x*x*x;
    return 0.5f*x*(1.f + tanhf(0.7978845608028654f*(x + 0.044715f*x3)));
}

__device__ __forceinline__ uint32_t f2tf(float f) {
    uint32_t r;
    asm("cvt.rna.tf32.f32 %0, %1;" : "=r"(r) : "f"(f));
    return r;
}

__device__ __forceinline__ void mma_tf32(float* d, const uint32_t* a, const uint32_t* b) {
    asm volatile(
        "mma.sync.aligned.m16n8k8.row.col.f32.tf32.tf32.f32 "
        "{%0,%1,%2,%3}, {%4,%5,%6,%7}, {%8,%9}, {%0,%1,%2,%3};\n"
        : "+f"(d[0]), "+f"(d[1]), "+f"(d[2]), "+f"(d[3])
        : "r"(a[0]), "r"(a[1]), "r"(a[2]), "r"(a[3]), "r"(b[0]), "r"(b[1]));
}

// ---------------- copy x -> out ----------------------------------------------
__global__ void copy_k(const float* __restrict__ in, float* __restrict__ out) {
    int i = blockIdx.x*blockDim.x + threadIdx.x;
    ((float4*)out)[i] = ((const float4*)in)[i];
}

// ---------------- mod = silu(c) @ w_ada + b_ada  [B,6C] ----------------------
__global__ void mod_k(const float* __restrict__ c, const float* __restrict__ w,
                      const float* __restrict__ bias, float* __restrict__ mod) {
    __shared__ float sc[B_][C_];
    int tid = threadIdx.x;
    for (int i = tid; i < B_*C_; i += 256) {
        float v = c[i];
        sc[i>>10][i&1023] = v / (1.f + __expf(-v));
    }
    __syncthreads();
    int col = blockIdx.x*256 + tid;
    float acc[B_];
    #pragma unroll
    for (int b = 0; b < B_; b++) acc[b] = 0.f;
    for (int k = 0; k < C_; k++) {
        float wv = w[(size_t)k*SIXC + col];
        #pragma unroll
        for (int b = 0; b < B_; b++) acc[b] += sc[b][k]*wv;
    }
    float bb = bias[col];
    #pragma unroll
    for (int b = 0; b < B_; b++) mod[b*SIXC + col] = acc[b] + bb;
}

// ---------------- LN (no affine) + modulate ----------------------------------
__global__ void ln_mod_k(const float* __restrict__ x, const float* __restrict__ mod,
                         int shiftOff, int scaleOff, float* __restrict__ out) {
    int row = blockIdx.x;
    int b   = row & (B_-1);
    const float* xr = x + (size_t)row*C_;
    float s = 0.f, s2 = 0.f;
    for (int i = threadIdx.x; i < C_; i += 256) {
        float v = xr[i]; s += v; s2 += v*v;
    }
    #pragma unroll
    for (int o = 16; o; o >>= 1) {
        s  += __shfl_xor_sync(0xffffffffu, s,  o);
        s2 += __shfl_xor_sync(0xffffffffu, s2, o);
    }
    __shared__ float red[2][8];
    int w = threadIdx.x >> 5, ln = threadIdx.x & 31;
    if (ln == 0) { red[0][w] = s; red[1][w] = s2; }
    __syncthreads();
    s = 0.f; s2 = 0.f;
    #pragma unroll
    for (int i = 0; i < 8; i++) { s += red[0][i]; s2 += red[1][i]; }
    float mu   = s * (1.f/C_);
    float var  = s2 * (1.f/C_) - mu*mu;
    float rstd = rsqrtf(var + 1e-6f);
    const float* sh = mod + b*SIXC + shiftOff;
    const float* sc = mod + b*SIXC + scaleOff;
    float* orow = out + (size_t)row*C_;
    for (int i = threadIdx.x; i < C_; i += 256)
        orow[i] = (xr[i]-mu)*rstd*(1.f+sc[i]) + sh[i];
}

// ---------------- tf32 tensor GEMM 128x128, BK=16, 256 thr -------------------
#define SA 20
#define SB 136
template<int EPI>
__global__ void __launch_bounds__(256, 2)
tgemm_k(const float* __restrict__ A, const float* __restrict__ W,
        const float* __restrict__ bias, float* __restrict__ out,
        const float* __restrict__ gate, int K, int N) {
    __shared__ uint32_t As[2][128*SA];
    __shared__ uint32_t Bs[2][16*SB];

    int tid  = threadIdx.x;
    int wid  = tid >> 5, lane = tid & 31;
    int g    = lane >> 2, tig = lane & 3;
    int wm   = wid >> 2, wn = wid & 3;
    int row0 = blockIdx.y*128, col0 = blockIdx.x*128;

    int ar0 = tid >> 2, avv = tid & 3;
    const float* Ap0 = A + (size_t)(row0 + ar0     )*K + 4*avv;
    const float* Ap1 = A + (size_t)(row0 + ar0 + 64)*K + 4*avv;
    int bk0 = tid >> 5, bvv = tid & 31;
    const float* Wp0 = W + (size_t)(bk0    )*N + col0 + 4*bvv;
    const float* Wp1 = W + (size_t)(bk0 + 8)*N + col0 + 4*bvv;

    float acc[4][4][4];
    #pragma unroll
    for (int i = 0; i < 4; i++)
        #pragma unroll
        for (int j = 0; j < 4; j++)
            #pragma unroll
            for (int q = 0; q < 4; q++) acc[i][j][q] = 0.f;

    float4 a0g = *(const float4*)Ap0;
    float4 a1g = *(const float4*)Ap1;
    float4 b0g = *(const float4*)Wp0;
    float4 b1g = *(const float4*)Wp1;

    {
        uint32_t* d0 = &As[0][ ar0      *SA + 4*avv];
        d0[0]=f2tf(a0g.x); d0[1]=f2tf(a0g.y); d0[2]=f2tf(a0g.z); d0[3]=f2tf(a0g.w);
        uint32_t* d1 = &As[0][(ar0 + 64)*SA + 4*avv];
        d1[0]=f2tf(a1g.x); d1[1]=f2tf(a1g.y); d1[2]=f2tf(a1g.z); d1[3]=f2tf(a1g.w);
        uint32_t* e0 = &Bs[0][ bk0     *SB + 4*bvv];
        e0[0]=f2tf(b0g.x); e0[1]=f2tf(b0g.y); e0[2]=f2tf(b0g.z); e0[3]=f2tf(b0g.w);
        uint32_t* e1 = &Bs[0][(bk0 + 8)*SB + 4*bvv];
        e1[0]=f2tf(b1g.x); e1[1]=f2tf(b1g.y); e1[2]=f2tf(b1g.z); e1[3]=f2tf(b1g.w);
    }
    __syncthreads();

    int buf = 0;
    int nchunk = K >> 4;
    for (int ch = 0; ch < nchunk; ch++) {
        bool more = (ch + 1 < nchunk);
        if (more) {
            Ap0 += 16; Ap1 += 16;
            Wp0 += (size_t)16*N; Wp1 += (size_t)16*N;
            a0g = *(const float4*)Ap0;
            a1g = *(const float4*)Ap1;
            b0g = *(const float4*)Wp0;
            b1g = *(const float4*)Wp1;
        }

        #pragma unroll
        for (int ks = 0; ks < 16; ks += 8) {
            uint32_t af[4][4], bf[4][2];
            #pragma unroll
            for (int mt = 0; mt < 4; mt++) {
                int m0 = wm*64 + mt*16;
                const uint32_t* p = &As[buf][(m0 + g)*SA + ks + tig];
                af[mt][0] = p[0];
                af[mt][2] = p[4];
                af[mt][1] = p[8*SA];
                af[mt][3] = p[8*SA + 4];
            }
            #pragma unroll
            for (int nt = 0; nt < 4; nt++) {
                int n0 = wn*32 + nt*8 + g;
                bf[nt][0] = Bs[buf][(ks + tig    )*SB + n0];
                bf[nt][1] = Bs[buf][(ks + tig + 4)*SB + n0];
            }
            #pragma unroll
            for (int mt = 0; mt < 4; mt++)
                #pragma unroll
                for (int nt = 0; nt < 4; nt++)
                    mma_tf32(acc[mt][nt], af[mt], bf[nt]);
        }

        if (more) {
            int nb = buf ^ 1;
            uint32_t* d0 = &As[nb][ ar0      *SA + 4*avv];
            d0[0]=f2tf(a0g.x); d0[1]=f2tf(a0g.y); d0[2]=f2tf(a0g.z); d0[3]=f2tf(a0g.w);
            uint32_t* d1 = &As[nb][(ar0 + 64)*SA + 4*avv];
            d1[0]=f2tf(a1g.x); d1[1]=f2tf(a1g.y); d1[2]=f2tf(a1g.z); d1[3]=f2tf(a1g.w);
            uint32_t* e0 = &Bs[nb][ bk0     *SB + 4*bvv];
            e0[0]=f2tf(b0g.x); e0[1]=f2tf(b0g.y); e0[2]=f2tf(b0g.z); e0[3]=f2tf(b0g.w);
            uint32_t* e1 = &Bs[nb][(bk0 + 8)*SB + 4*bvv];
            e1[0]=f2tf(b1g.x); e1[1]=f2tf(b1g.y); e1[2]=f2tf(b1g.z); e1[3]=f2tf(b1g.w);
        }
        __syncthreads();
        buf ^= 1;
    }

    #pragma unroll
    for (int mt = 0; mt < 4; mt++) {
        int rbase = row0 + wm*64 + mt*16 + g;
        #pragma unroll
        for (int half = 0; half < 2; half++) {
            int rr = rbase + 8*half;
            int bb = rr & (B_-1);
            float* orow = out + (size_t)rr*N;
            #pragma unroll
            for (int nt = 0; nt < 4; nt++) {
                int cb = col0 + wn*32 + nt*8 + 2*tig;
                float v0 = acc[mt][nt][2*half + 0] + bias[cb];
                float v1 = acc[mt][nt][2*half + 1] + bias[cb+1];
                if (EPI == 0) {
                    orow[cb]   = v0;
                    orow[cb+1] = v1;
                } else if (EPI == 1) {
                    orow[cb]   = gelu_tanh(v0);
                    orow[cb+1] = gelu_tanh(v1);
                } else {
                    orow[cb]   += gate[bb*SIXC + cb  ]*v0;
                    orow[cb+1] += gate[bb*SIXC + cb+1]*v1;
                }
            }
        }
    }
}

// ---------------- tf32 tensor-core flash attention ---------------------------
// grid (T/64, H, B), 256 thr (8 warps: wm=wid>>1 row-tile, wn=wid&1 col-half).
// Qs/Ks/Ss stride 68 (conflict-free frag LDS), Vs stride 72.
#define AQS 68
#define AVS 72
__global__ void __launch_bounds__(256, 2)
fattn_k(const float* __restrict__ Q, const float* __restrict__ Kx,
        const float* __restrict__ Vx, const int* __restrict__ mask,
        float* __restrict__ Y, int Tk) {
    extern __shared__ uint32_t smu[];
    uint32_t* Qs = smu;
    uint32_t* Ks = Qs + 64*AQS;
    uint32_t* Vs = Ks + 64*AQS;
    uint32_t* Ss = Vs + 64*AVS;
    float*    Ssf  = (float*)Ss;
    float*    mrow = (float*)(Ss + 64*AQS);
    float*    lrow = mrow + 64;
    float*    srow = lrow + 64;
    int*      Ms   = (int*)(srow + 64);

    int tid  = threadIdx.x;
    int lane = tid & 31, wid = tid >> 5;
    int g    = lane >> 2, tig = lane & 3;
    int wm   = wid >> 1, wn = wid & 1;
    int q0 = blockIdx.x*64, h = blockIdx.y, b = blockIdx.z;
    size_t hoff = (size_t)h*D_;

    // load Q tile (tf32)
    #pragma unroll
    for (int p = 0; p < 4; p++) {
        int idx = tid + p*256;
        int r = idx >> 4, c4 = (idx & 15)*4;
        float4 v = *(const float4*)&Q[((size_t)(q0+r)*B_ + b)*C_ + hoff + c4];
        uint32_t* d = &Qs[r*AQS + c4];
        d[0]=f2tf(v.x); d[1]=f2tf(v.y); d[2]=f2tf(v.z); d[3]=f2tf(v.w);
    }
    if (tid < 64) { mrow[tid] = -1e30f; lrow[tid] = 0.f; }

    float oacc[4][4];
    #pragma unroll
    for (int i = 0; i < 4; i++)
        #pragma unroll
        for (int j = 0; j < 4; j++) oacc[i][j] = 0.f;
    __syncthreads();

    for (int k0 = 0; k0 < Tk; k0 += 64) {
        // load K,V tiles
        #pragma unroll
        for (int p = 0; p < 4; p++) {
            int idx = tid + p*256;
            int r = idx >> 4, c4 = (idx & 15)*4;
            size_t gi = ((size_t)(k0+r)*B_ + b)*C_ + hoff + c4;
            float4 kv = *(const float4*)&Kx[gi];
            float4 vv = *(const float4*)&Vx[gi];
            uint32_t* dk = &Ks[r*AQS + c4];
            dk[0]=f2tf(kv.x); dk[1]=f2tf(kv.y); dk[2]=f2tf(kv.z); dk[3]=f2tf(kv.w);
            uint32_t* dv = &Vs[r*AVS + c4];
            dv[0]=f2tf(vv.x); dv[1]=f2tf(vv.y); dv[2]=f2tf(vv.z); dv[3]=f2tf(vv.w);
        }
        if (tid < 64) Ms[tid] = mask[(size_t)b*Tk + k0 + tid];
        __syncthreads();

        // ---- S = Q K^T (warp: rows wm*16..+15, cols wn*32..+31) ----
        float sacc[4][4];
        #pragma unroll
        for (int i = 0; i < 4; i++)
            #pragma unroll
            for (int j = 0; j < 4; j++) sacc[i][j] = 0.f;
        #pragma unroll
        for (int ks = 0; ks < 64; ks += 8) {
            uint32_t af[4];
            const uint32_t* qp = &Qs[(wm*16 + g)*AQS + ks + tig];
            af[0] = qp[0]; af[1] = qp[8*AQS]; af[2] = qp[4]; af[3] = qp[8*AQS + 4];
            #pragma unroll
            for (int nt = 0; nt < 4; nt++) {
                int n0 = wn*32 + nt*8;
                uint32_t bf[2];
                bf[0] = Ks[(n0 + g)*AQS + ks + tig];
                bf[1] = Ks[(n0 + g)*AQS + ks + tig + 4];
                mma_tf32(sacc[nt], af, bf);
            }
        }
        #pragma unroll
        for (int nt = 0; nt < 4; nt++) {
            int cc = wn*32 + nt*8 + 2*tig;
            int r0 = wm*16 + g;
            *(float2*)&Ssf[ r0     *AQS + cc] = make_float2(sacc[nt][0], sacc[nt][1]);
            *(float2*)&Ssf[(r0 + 8)*AQS + cc] = make_float2(sacc[nt][2], sacc[nt][3]);
        }
        __syncthreads();

        // ---- online softmax (thread: row tid>>2, 16 cols) ----
        {
            int r  = tid >> 2, c0 = (tid & 3)*16;
            float s[16];
            #pragma unroll
            for (int j = 0; j < 16; j++)
                s[j] = Ms[c0 + j] ? -1e30f : Ssf[r*AQS + c0 + j]*0.125f;
            float mx = s[0];
            #pragma unroll
            for (int j = 1; j < 16; j++) mx = fmaxf(mx, s[j]);
            mx = fmaxf(mx, __shfl_xor_sync(0xffffffffu, mx, 1));
            mx = fmaxf(mx, __shfl_xor_sync(0xffffffffu, mx, 2));
            float mold = mrow[r];
            float mnew = fmaxf(mold, mx);
            float rs = 0.f;
            #pragma unroll
            for (int j = 0; j < 16; j++) {
                float p = (s[j] > -1e29f) ? __expf(s[j] - mnew) : 0.f;
                rs += p;
                Ss[r*AQS + c0 + j] = f2tf(p);
            }
            rs += __shfl_xor_sync(0xffffffffu, rs, 1);
            rs += __shfl_xor_sync(0xffffffffu, rs, 2);
            if ((tid & 3) == 0) {
                float scl = __expf(mold - mnew);
                lrow[r] = lrow[r]*scl + rs;
                mrow[r] = mnew;
                srow[r] = scl;
            }
        }
        __syncthreads();

        // ---- O = O*scale + P @ V ----
        float s0 = srow[wm*16 + g];
        float s1 = srow[wm*16 + g + 8];
        #pragma unroll
        for (int nt = 0; nt < 4; nt++) {
            oacc[nt][0] *= s0; oacc[nt][1] *= s0;
            oacc[nt][2] *= s1; oacc[nt][3] *= s1;
        }
        #pragma unroll
        for (int ks = 0; ks < 64; ks += 8) {
            uint32_t af[4];
            const uint32_t* pp = &Ss[(wm*16 + g)*AQS + ks + tig];
            af[0] = pp[0]; af[1] = pp[8*AQS]; af[2] = pp[4]; af[3] = pp[8*AQS + 4];
            #pragma unroll
            for (int nt = 0; nt < 4; nt++) {
                int n0 = wn*32 + nt*8;
                uint32_t bf[2];
                bf[0] = Vs[(ks + tig    )*AVS + n0 + g];
                bf[1] = Vs[(ks + tig + 4)*AVS + n0 + g];
                mma_tf32(oacc[nt], af, bf);
            }
        }
        __syncthreads();
    }

    // epilogue: O / l
    float inv0 = 1.f / lrow[wm*16 + g];
    float inv1 = 1.f / lrow[wm*16 + g + 8];
    int r0 = q0 + wm*16 + g;
    #pragma unroll
    for (int nt = 0; nt < 4; nt++) {
        int dd = wn*32 + nt*8 + 2*tig;
        *(float2*)&Y[((size_t) r0     *B_ + b)*C_ + hoff + dd] =
            make_float2(oacc[nt][0]*inv0, oacc[nt][1]*inv0);
        *(float2*)&Y[((size_t)(r0 + 8)*B_ + b)*C_ + hoff + dd] =
            make_float2(oacc[nt][2]*inv1, oacc[nt][3]*inv1);
    }
}

// ---------------- launch -----------------------------------------------------
extern "C" void kernel_launch(void* const* d_in, const int* in_sizes, int n_in,
                              void* d_out, int out_size) {
    const float* x     = (const float*)d_in[0];
    const float* c     = (const float*)d_in[1];
    const int*   pmask = (const int*)  d_in[2];
    const float* audio = (const float*)d_in[3];
    const int*   amask = (const int*)  d_in[4];
    const float* w_ada = (const float*)d_in[5];
    const float* b_ada = (const float*)d_in[6];
    const float* wq = (const float*)d_in[7];   const float* bq = (const float*)d_in[8];
    const float* wk = (const float*)d_in[9];   const float* bk = (const float*)d_in[10];
    const float* wv = (const float*)d_in[11];  const float* bv = (const float*)d_in[12];
    const float* wo = (const float*)d_in[13];  const float* bo = (const float*)d_in[14];
    const float* cwq = (const float*)d_in[15]; const float* cbq = (const float*)d_in[16];
    const float* cwk = (const float*)d_in[17]; const float* cbk = (const float*)d_in[18];
    const float* cwv = (const float*)d_in[19]; const float* cbv = (const float*)d_in[20];
    const float* cwo = (const float*)d_in[21]; const float* cbo = (const float*)d_in[22];
    const float* w1 = (const float*)d_in[23];  const float* b1 = (const float*)d_in[24];
    const float* w2 = (const float*)d_in[25];  const float* b2 = (const float*)d_in[26];
    float* out = (float*)d_out;

    float *modp, *lnp, *qp, *kp, *vp, *yp, *hp;
    cudaGetSymbolAddress((void**)&modp, g_mod);
    cudaGetSymbolAddress((void**)&lnp,  g_ln);
    cudaGetSymbolAddress((void**)&qp,   g_q);
    cudaGetSymbolAddress((void**)&kp,   g_k);
    cudaGetSymbolAddress((void**)&vp,   g_v);
    cudaGetSymbolAddress((void**)&yp,   g_y);
    cudaGetSymbolAddress((void**)&hp,   g_h);

    int attn_smem = (3*64*AQS + 64*AVS + 3*64)*sizeof(uint32_t) + 64*sizeof(int);
    cudaFuncSetAttribute(fattn_k, cudaFuncAttributeMaxDynamicSharedMemorySize, attn_smem);

    dim3 gC(C_/128, R_/128);
    dim3 gM(M_/128, R_/128);
    dim3 gA(T_/64, H_, B_);

    copy_k<<<(R_*C_)/1024, 256>>>(x, out);
    mod_k<<<SIXC/256, 256>>>(c, w_ada, b_ada, modp);

    // ---- self attention ----
    ln_mod_k<<<R_, 256>>>(out, modp, 0, C_, lnp);
    tgemm_k<0><<<gC, 256>>>(lnp, wq, bq, qp, nullptr, C_, C_);
    tgemm_k<0><<<gC, 256>>>(lnp, wk, bk, kp, nullptr, C_, C_);
    tgemm_k<0><<<gC, 256>>>(lnp, wv, bv, vp, nullptr, C_, C_);
    fattn_k<<<gA, 256, attn_smem>>>(qp, kp, vp, pmask, yp, T_);
    tgemm_k<2><<<gC, 256>>>(yp, wo, bo, out, modp + 2*C_, C_, C_);

    // ---- cross attention (reuses msa shift/scale/gate) ----
    ln_mod_k<<<R_, 256>>>(out, modp, 0, C_, lnp);
    tgemm_k<0><<<gC, 256>>>(lnp,   cwq, cbq, qp, nullptr, C_, C_);
    tgemm_k<0><<<gC, 256>>>(audio, cwk, cbk, kp, nullptr, C_, C_);
    tgemm_k<0><<<gC, 256>>>(audio, cwv, cbv, vp, nullptr, C_, C_);
    fattn_k<<<gA, 256, attn_smem>>>(qp, kp, vp, amask, yp, TA_);
    tgemm_k<2><<<gC, 256>>>(yp, cwo, cbo, out, modp + 2*C_, C_, C_);

    // ---- MLP ----
    ln_mod_k<<<R_, 256>>>(out, modp, 3*C_, 4*C_, lnp);
    tgemm_k<1><<<gM, 256>>>(lnp, w1, b1, hp, nullptr, C_, M_);
    tgemm_k<2><<<gC, 256>>>(hp, w2, b2, out, modp + 5*C_, M_, C_);
}

// round 5
// speedup vs baseline: 6.1317x; 1.3539x over previous
#include <cuda_runtime.h>
#include <cuda_fp16.h>
#include <math.h>
#include <stdint.h>

#define T_  1024
#define B_  8
#define C_  1024
#define H_  16
#define D_  64
#define M_  4096
#define TA_ 1024
#define R_  (T_*B_)
#define SIXC (6*C_)

// ---------------- scratch (device globals) -----------------------------------
__device__ float g_mod[B_*SIXC];
__device__ float g_ln [R_*C_];
__device__ float g_qkv[(size_t)R_*3*C_];   // merged q|k|v, row stride 3C
__device__ float g_y  [R_*C_];
__device__ float g_h  [(size_t)R_*M_];

// ---------------- helpers ----------------------------------------------------
__device__ __forceinline__ float gelu_tanh(float x) {
    float x3 = x*x*x;
    return 0.5f*x*(1.f + tanhf(0.7978845608028654f*(x + 0.044715f*x3)));
}

__device__ __forceinline__ uint32_t f2h2(float lo, float hi) {
    __half2 h = __floats2half2_rn(lo, hi);
    return *reinterpret_cast<uint32_t*>(&h);
}

__device__ __forceinline__ void mma_f16(float* d, const uint32_t* a, const uint32_t* b) {
    asm volatile(
        "mma.sync.aligned.m16n8k16.row.col.f32.f16.f16.f32 "
        "{%0,%1,%2,%3}, {%4,%5,%6,%7}, {%8,%9}, {%0,%1,%2,%3};\n"
        : "+f"(d[0]), "+f"(d[1]), "+f"(d[2]), "+f"(d[3])
        : "r"(a[0]), "r"(a[1]), "r"(a[2]), "r"(a[3]), "r"(b[0]), "r"(b[1]));
}

__device__ __forceinline__ void ldsm4(uint32_t* r, uint32_t addr) {
    asm volatile("ldmatrix.sync.aligned.m8n8.x4.shared.b16 {%0,%1,%2,%3}, [%4];"
        : "=r"(r[0]), "=r"(r[1]), "=r"(r[2]), "=r"(r[3]) : "r"(addr));
}
__device__ __forceinline__ void ldsm4t(uint32_t* r, uint32_t addr) {
    asm volatile("ldmatrix.sync.aligned.m8n8.x4.trans.shared.b16 {%0,%1,%2,%3}, [%4];"
        : "=r"(r[0]), "=r"(r[1]), "=r"(r[2]), "=r"(r[3]) : "r"(addr));
}

// ---------------- copy x -> out ----------------------------------------------
__global__ void copy_k(const float* __restrict__ in, float* __restrict__ out) {
    int i = blockIdx.x*blockDim.x + threadIdx.x;
    ((float4*)out)[i] = ((const float4*)in)[i];
}

// ---------------- mod = silu(c) @ w_ada + b_ada ------------------------------
__global__ void mod_k(const float* __restrict__ c, const float* __restrict__ w,
                      const float* __restrict__ bias, float* __restrict__ mod) {
    __shared__ float sc[B_][C_];
    int tid = threadIdx.x;
    for (int i = tid; i < B_*C_; i += 256) {
        float v = c[i];
        sc[i>>10][i&1023] = v / (1.f + __expf(-v));
    }
    __syncthreads();
    int col = blockIdx.x*256 + tid;
    float acc[B_];
    #pragma unroll
    for (int b = 0; b < B_; b++) acc[b] = 0.f;
    for (int k = 0; k < C_; k++) {
        float wv = w[(size_t)k*SIXC + col];
        #pragma unroll
        for (int b = 0; b < B_; b++) acc[b] += sc[b][k]*wv;
    }
    float bb = bias[col];
    #pragma unroll
    for (int b = 0; b < B_; b++) mod[b*SIXC + col] = acc[b] + bb;
}

// ---------------- LN (no affine) + modulate ----------------------------------
__global__ void ln_mod_k(const float* __restrict__ x, const float* __restrict__ mod,
                         int shiftOff, int scaleOff, float* __restrict__ out) {
    int row = blockIdx.x;
    int b   = row & (B_-1);
    const float* xr = x + (size_t)row*C_;
    float s = 0.f, s2 = 0.f;
    for (int i = threadIdx.x; i < C_; i += 256) {
        float v = xr[i]; s += v; s2 += v*v;
    }
    #pragma unroll
    for (int o = 16; o; o >>= 1) {
        s  += __shfl_xor_sync(0xffffffffu, s,  o);
        s2 += __shfl_xor_sync(0xffffffffu, s2, o);
    }
    __shared__ float red[2][8];
    int w = threadIdx.x >> 5, ln = threadIdx.x & 31;
    if (ln == 0) { red[0][w] = s; red[1][w] = s2; }
    __syncthreads();
    s = 0.f; s2 = 0.f;
    #pragma unroll
    for (int i = 0; i < 8; i++) { s += red[0][i]; s2 += red[1][i]; }
    float mu   = s * (1.f/C_);
    float var  = s2 * (1.f/C_) - mu*mu;
    float rstd = rsqrtf(var + 1e-6f);
    const float* sh = mod + b*SIXC + shiftOff;
    const float* sc = mod + b*SIXC + scaleOff;
    float* orow = out + (size_t)row*C_;
    for (int i = threadIdx.x; i < C_; i += 256)
        orow[i] = (xr[i]-mu)*rstd*(1.f+sc[i]) + sh[i];
}

// ---------------- fp16 tensor GEMM body (128x128, BK=16, 256 thr) ------------
// As: half2 [m][k2] row stride SAW=20 u32 (80B: ldmatrix conflict-free)
// Bs: half2 [k][n2] row stride SBW=68 u32 (272B: ldmatrix.trans conflict-free)
#define SAW 20
#define SBW 68
template<int EPI>
__device__ __forceinline__ void gemm_body(
    uint32_t* AsS, uint32_t* BsS,
    const float* __restrict__ A, const float* __restrict__ W,
    const float* __restrict__ bias, float* __restrict__ out,
    const float* __restrict__ gate,
    int K, int N, int row0, int col0, size_t ostride, int ocol0)
{
    int tid  = threadIdx.x;
    int lane = tid & 31, wid = tid >> 5;
    int g    = lane >> 2, tig = lane & 3;
    int wm   = wid >> 2, wn = wid & 3;       // warp tile 64m x 32n

    // staging: A row ar=tid>>1, k-half (tid&1)*8 ; B row bk=tid>>4, n8=(tid&15)*8
    int ar = tid >> 1, ah = tid & 1;
    int bk = tid >> 4, n8 = (tid & 15)*8;
    const float* Ap = A + (size_t)(row0 + ar)*K + ah*8;
    const float* Wp = W + (size_t)bk*N + col0 + n8;

    uint32_t sA0 = (uint32_t)__cvta_generic_to_shared(AsS);
    uint32_t sB0 = (uint32_t)__cvta_generic_to_shared(BsS);

    float acc[4][4][4];
    #pragma unroll
    for (int i = 0; i < 4; i++)
        #pragma unroll
        for (int j = 0; j < 4; j++)
            #pragma unroll
            for (int q = 0; q < 4; q++) acc[i][j][q] = 0.f;

    float4 a0 = *(const float4*)Ap;
    float4 a1 = *(const float4*)(Ap + 4);
    float4 b0 = *(const float4*)Wp;
    float4 b1 = *(const float4*)(Wp + 4);

    {
        uint32_t* da = AsS + ar*SAW + ah*4;
        *(uint4*)da = make_uint4(f2h2(a0.x,a0.y), f2h2(a0.z,a0.w),
                                 f2h2(a1.x,a1.y), f2h2(a1.z,a1.w));
        uint32_t* db = BsS + bk*SBW + (n8>>1);
        *(uint4*)db = make_uint4(f2h2(b0.x,b0.y), f2h2(b0.z,b0.w),
                                 f2h2(b1.x,b1.y), f2h2(b1.z,b1.w));
    }
    __syncthreads();

    int buf = 0;
    int nchunk = K >> 4;
    for (int ch = 0; ch < nchunk; ch++) {
        bool more = (ch + 1 < nchunk);
        if (more) {
            Ap += 16; Wp += (size_t)16*N;
            a0 = *(const float4*)Ap;
            a1 = *(const float4*)(Ap + 4);
            b0 = *(const float4*)Wp;
            b1 = *(const float4*)(Wp + 4);
        }

        uint32_t sA = sA0 + buf*(128*SAW*4);
        uint32_t sB = sB0 + buf*(16*SBW*4);

        // A fragments: 4 m-tiles via ldmatrix.x4
        uint32_t af[4][4];
        #pragma unroll
        for (int mt = 0; mt < 4; mt++) {
            uint32_t addr = sA + ((wm*64 + mt*16 + (lane & 15))*SAW + ((lane >> 4) << 2))*4;
            ldsm4(af[mt], addr);
        }
        // B fragments: 2 ldmatrix.x4.trans cover 4 n-tiles
        uint32_t bq[2][4];
        #pragma unroll
        for (int hf = 0; hf < 2; hf++) {
            uint32_t addr = sB + ((lane & 15)*SBW + (wn*16 + hf*8) + ((lane >> 4) << 2))*4;
            ldsm4t(bq[hf], addr);
        }
        #pragma unroll
        for (int mt = 0; mt < 4; mt++)
            #pragma unroll
            for (int nt = 0; nt < 4; nt++)
                mma_f16(acc[mt][nt], af[mt], &bq[nt >> 1][(nt & 1)*2]);

        if (more) {
            uint32_t* da = AsS + (buf^1)*(128*SAW) + ar*SAW + ah*4;
            *(uint4*)da = make_uint4(f2h2(a0.x,a0.y), f2h2(a0.z,a0.w),
                                     f2h2(a1.x,a1.y), f2h2(a1.z,a1.w));
            uint32_t* db = BsS + (buf^1)*(16*SBW) + bk*SBW + (n8>>1);
            *(uint4*)db = make_uint4(f2h2(b0.x,b0.y), f2h2(b0.z,b0.w),
                                     f2h2(b1.x,b1.y), f2h2(b1.z,b1.w));
        }
        __syncthreads();
        buf ^= 1;
    }

    #pragma unroll
    for (int mt = 0; mt < 4; mt++) {
        int rbase = row0 + wm*64 + mt*16 + g;
        #pragma unroll
        for (int half = 0; half < 2; half++) {
            int rr = rbase + 8*half;
            int bb = rr & (B_-1);
            float* orow = out + (size_t)rr*ostride + ocol0;
            #pragma unroll
            for (int nt = 0; nt < 4; nt++) {
                int cl = col0 + wn*32 + nt*8 + 2*tig;
                float v0 = acc[mt][nt][2*half + 0] + bias[cl];
                float v1 = acc[mt][nt][2*half + 1] + bias[cl+1];
                if (EPI == 0) {
                    orow[cl]   = v0;
                    orow[cl+1] = v1;
                } else if (EPI == 1) {
                    orow[cl]   = gelu_tanh(v0);
                    orow[cl+1] = gelu_tanh(v1);
                } else {
                    orow[cl]   += gate[bb*SIXC + cl  ]*v0;
                    orow[cl+1] += gate[bb*SIXC + cl+1]*v1;
                }
            }
        }
    }
}

template<int EPI>
__global__ void __launch_bounds__(256, 2)
hgemm_k(const float* __restrict__ A, const float* __restrict__ W,
        const float* __restrict__ bias, float* __restrict__ out,
        const float* __restrict__ gate, int K, int N) {
    __shared__ __align__(16) uint32_t As[2*128*SAW];
    __shared__ __align__(16) uint32_t Bs[2*16*SBW];
    gemm_body<EPI>(As, Bs, A, W, bias, out, gate, K, N,
                   blockIdx.y*128, blockIdx.x*128, N, 0);
}

// merged q/k/v projection: grid.x = 24 (3 mats x 8 col-blocks); out stride 3C
__global__ void __launch_bounds__(256, 2)
hgemm_qkv_k(const float* __restrict__ A0, const float* __restrict__ A12,
            const float* __restrict__ W0, const float* __restrict__ W1,
            const float* __restrict__ W2,
            const float* __restrict__ b0, const float* __restrict__ b1,
            const float* __restrict__ b2,
            float* __restrict__ out, int K) {
    __shared__ __align__(16) uint32_t As[2*128*SAW];
    __shared__ __align__(16) uint32_t Bs[2*16*SBW];
    int sel = blockIdx.x >> 3;
    int nb  = blockIdx.x & 7;
    const float* A    = (sel == 0) ? A0 : A12;
    const float* W    = (sel == 0) ? W0 : (sel == 1) ? W1 : W2;
    const float* bias = (sel == 0) ? b0 : (sel == 1) ? b1 : b2;
    gemm_body<0>(As, Bs, A, W, bias, out, nullptr, K, C_,
                 blockIdx.y*128, nb*128, 3*C_, sel*C_);
}

// ---------------- fp16 tensor-core flash attention ---------------------------
// Qs/Ks/Vs/Ps: half2 [row][d2 or key2], stride AQW=36 u32 (144B)
// Ssf: fp32 scores, stride SSW=68
#define AQW 36
#define SSW 68
__global__ void __launch_bounds__(256, 2)
fattn_k(const float* __restrict__ QKV, const int* __restrict__ mask,
        float* __restrict__ Y, int Tk) {
    extern __shared__ uint32_t smu[];
    uint32_t* Qs = smu;
    uint32_t* Ks = Qs + 64*AQW;
    uint32_t* Vs = Ks + 64*AQW;
    uint32_t* Ps = Vs + 64*AQW;
    float*    Ssf  = (float*)(Ps + 64*AQW);
    float*    mrow = Ssf + 64*SSW;
    float*    lrow = mrow + 64;
    float*    srow = lrow + 64;
    int*      Ms   = (int*)(srow + 64);

    int tid  = threadIdx.x;
    int lane = tid & 31, wid = tid >> 5;
    int g    = lane >> 2, tig = lane & 3;
    int wm   = wid >> 1, wn = wid & 1;
    int q0 = blockIdx.x*64, h = blockIdx.y, b = blockIdx.z;
    size_t hoff = (size_t)h*D_;
    const int RS = 3*C_;
    const float* Kp = QKV + C_;
    const float* Vp = QKV + 2*C_;

    uint32_t vbase = (uint32_t)__cvta_generic_to_shared(Vs);

    // load Q tile
    #pragma unroll
    for (int p = 0; p < 4; p++) {
        int idx = tid + p*256;
        int r = idx >> 4, c4 = (idx & 15)*4;
        float4 v = *(const float4*)&QKV[((size_t)(q0+r)*B_ + b)*RS + hoff + c4];
        uint32_t* d = &Qs[r*AQW + (c4>>1)];
        d[0] = f2h2(v.x, v.y); d[1] = f2h2(v.z, v.w);
    }
    if (tid < 64) { mrow[tid] = -1e30f; lrow[tid] = 0.f; }

    float oacc[4][4];
    #pragma unroll
    for (int i = 0; i < 4; i++)
        #pragma unroll
        for (int j = 0; j < 4; j++) oacc[i][j] = 0.f;
    __syncthreads();

    for (int k0 = 0; k0 < Tk; k0 += 64) {
        // load K,V tiles
        #pragma unroll
        for (int p = 0; p < 4; p++) {
            int idx = tid + p*256;
            int r = idx >> 4, c4 = (idx & 15)*4;
            size_t gi = ((size_t)(k0+r)*B_ + b)*RS + hoff + c4;
            float4 kv = *(const float4*)&Kp[gi];
            float4 vv = *(const float4*)&Vp[gi];
            uint32_t* dk = &Ks[r*AQW + (c4>>1)];
            dk[0] = f2h2(kv.x, kv.y); dk[1] = f2h2(kv.z, kv.w);
            uint32_t* dv = &Vs[r*AQW + (c4>>1)];
            dv[0] = f2h2(vv.x, vv.y); dv[1] = f2h2(vv.z, vv.w);
        }
        if (tid < 64) Ms[tid] = mask[(size_t)b*Tk + k0 + tid];
        __syncthreads();

        // ---- S = Q K^T : warp rows wm*16..+15, cols wn*32..+31 ----
        float sacc[4][4];
        #pragma unroll
        for (int i = 0; i < 4; i++)
            #pragma unroll
            for (int j = 0; j < 4; j++) sacc[i][j] = 0.f;
        #pragma unroll
        for (int ks = 0; ks < 4; ks++) {
            uint32_t af[4];
            const uint32_t* qp = &Qs[(wm*16 + g)*AQW + ks*8 + tig];
            af[0] = qp[0]; af[1] = qp[8*AQW]; af[2] = qp[4]; af[3] = qp[8*AQW + 4];
            #pragma unroll
            for (int nt = 0; nt < 4; nt++) {
                int nr = wn*32 + nt*8 + g;
                uint32_t bf[2];
                bf[0] = Ks[nr*AQW + ks*8 + tig];
                bf[1] = Ks[nr*AQW + ks*8 + tig + 4];
                mma_f16(sacc[nt], af, bf);
            }
        }
        #pragma unroll
        for (int nt = 0; nt < 4; nt++) {
            int cc = wn*32 + nt*8 + 2*tig;
            int r0 = wm*16 + g;
            *(float2*)&Ssf[ r0     *SSW + cc] = make_float2(sacc[nt][0], sacc[nt][1]);
            *(float2*)&Ssf[(r0 + 8)*SSW + cc] = make_float2(sacc[nt][2], sacc[nt][3]);
        }
        __syncthreads();

        // ---- online softmax: thread owns row tid>>2, cols (tid&3)*16.. ----
        {
            int r  = tid >> 2, c0 = (tid & 3)*16;
            float s[16];
            #pragma unroll
            for (int j = 0; j < 16; j++)
                s[j] = Ms[c0 + j] ? -1e30f : Ssf[r*SSW + c0 + j]*0.125f;
            float mx = s[0];
            #pragma unroll
            for (int j = 1; j < 16; j++) mx = fmaxf(mx, s[j]);
            mx = fmaxf(mx, __shfl_xor_sync(0xffffffffu, mx, 1));
            mx = fmaxf(mx, __shfl_xor_sync(0xffffffffu, mx, 2));
            float mold = mrow[r];
            float mnew = fmaxf(mold, mx);
            float p[16];
            float rs = 0.f;
            #pragma unroll
            for (int j = 0; j < 16; j++) {
                p[j] = (s[j] > -1e29f) ? __expf(s[j] - mnew) : 0.f;
                rs += p[j];
            }
            uint32_t* pr = &Ps[r*AQW + (c0>>1)];
            #pragma unroll
            for (int j = 0; j < 8; j++) pr[j] = f2h2(p[2*j], p[2*j+1]);
            rs += __shfl_xor_sync(0xffffffffu, rs, 1);
            rs += __shfl_xor_sync(0xffffffffu, rs, 2);
            if ((tid & 3) == 0) {
                float scl = __expf(mold - mnew);
                lrow[r] = lrow[r]*scl + rs;
                mrow[r] = mnew;
                srow[r] = scl;
            }
        }
        __syncthreads();

        // ---- O = O*scale + P @ V ----
        float s0 = srow[wm*16 + g];
        float s1 = srow[wm*16 + g + 8];
        #pragma unroll
        for (int nt = 0; nt < 4; nt++) {
            oacc[nt][0] *= s0; oacc[nt][1] *= s0;
            oacc[nt][2] *= s1; oacc[nt][3] *= s1;
        }
        #pragma unroll
        for (int ks = 0; ks < 4; ks++) {
            uint32_t af[4];
            const uint32_t* pp = &Ps[(wm*16 + g)*AQW + ks*8 + tig];
            af[0] = pp[0]; af[1] = pp[8*AQW]; af[2] = pp[4]; af[3] = pp[8*AQW + 4];
            uint32_t bq[2][4];
            #pragma unroll
            for (int hf = 0; hf < 2; hf++) {
                uint32_t addr = vbase +
                    ((ks*16 + (lane & 15))*AQW + (wn*16 + hf*8) + ((lane >> 4) << 2))*4;
                ldsm4t(bq[hf], addr);
            }
            #pragma unroll
            for (int nt = 0; nt < 4; nt++)
                mma_f16(oacc[nt], af, &bq[nt >> 1][(nt & 1)*2]);
        }
        __syncthreads();
    }

    // epilogue: O / l
    float inv0 = 1.f / lrow[wm*16 + g];
    float inv1 = 1.f / lrow[wm*16 + g + 8];
    int r0 = q0 + wm*16 + g;
    #pragma unroll
    for (int nt = 0; nt < 4; nt++) {
        int dd = wn*32 + nt*8 + 2*tig;
        *(float2*)&Y[((size_t) r0     *B_ + b)*C_ + hoff + dd] =
            make_float2(oacc[nt][0]*inv0, oacc[nt][1]*inv0);
        *(float2*)&Y[((size_t)(r0 + 8)*B_ + b)*C_ + hoff + dd] =
            make_float2(oacc[nt][2]*inv1, oacc[nt][3]*inv1);
    }
}

// ---------------- launch -----------------------------------------------------
extern "C" void kernel_launch(void* const* d_in, const int* in_sizes, int n_in,
                              void* d_out, int out_size) {
    const float* x     = (const float*)d_in[0];
    const float* c     = (const float*)d_in[1];
    const int*   pmask = (const int*)  d_in[2];
    const float* audio = (const float*)d_in[3];
    const int*   amask = (const int*)  d_in[4];
    const float* w_ada = (const float*)d_in[5];
    const float* b_ada = (const float*)d_in[6];
    const float* wq = (const float*)d_in[7];   const float* bq = (const float*)d_in[8];
    const float* wk = (const float*)d_in[9];   const float* bk = (const float*)d_in[10];
    const float* wv = (const float*)d_in[11];  const float* bv = (const float*)d_in[12];
    const float* wo = (const float*)d_in[13];  const float* bo = (const float*)d_in[14];
    const float* cwq = (const float*)d_in[15]; const float* cbq = (const float*)d_in[16];
    const float* cwk = (const float*)d_in[17]; const float* cbk = (const float*)d_in[18];
    const float* cwv = (const float*)d_in[19]; const float* cbv = (const float*)d_in[20];
    const float* cwo = (const float*)d_in[21]; const float* cbo = (const float*)d_in[22];
    const float* w1 = (const float*)d_in[23];  const float* b1 = (const float*)d_in[24];
    const float* w2 = (const float*)d_in[25];  const float* b2 = (const float*)d_in[26];
    float* out = (float*)d_out;

    float *modp, *lnp, *qkvp, *yp, *hp;
    cudaGetSymbolAddress((void**)&modp, g_mod);
    cudaGetSymbolAddress((void**)&lnp,  g_ln);
    cudaGetSymbolAddress((void**)&qkvp, g_qkv);
    cudaGetSymbolAddress((void**)&yp,   g_y);
    cudaGetSymbolAddress((void**)&hp,   g_h);

    int attn_smem = (4*64*AQW + 64*SSW + 3*64 + 64)*sizeof(uint32_t);
    cudaFuncSetAttribute(fattn_k, cudaFuncAttributeMaxDynamicSharedMemorySize, attn_smem);

    dim3 gQKV(24, 64);
    dim3 gC(8, 64);
    dim3 gM(32, 64);
    dim3 gA(T_/64, H_, B_);

    copy_k<<<(R_*C_)/1024, 256>>>(x, out);
    mod_k<<<SIXC/256, 256>>>(c, w_ada, b_ada, modp);

    // ---- self attention ----
    ln_mod_k<<<R_, 256>>>(out, modp, 0, C_, lnp);
    hgemm_qkv_k<<<gQKV, 256>>>(lnp, lnp, wq, wk, wv, bq, bk, bv, qkvp, C_);
    fattn_k<<<gA, 256, attn_smem>>>(qkvp, pmask, yp, T_);
    hgemm_k<2><<<gC, 256>>>(yp, wo, bo, out, modp + 2*C_, C_, C_);

    // ---- cross attention (reuses msa shift/scale/gate) ----
    ln_mod_k<<<R_, 256>>>(out, modp, 0, C_, lnp);
    hgemm_qkv_k<<<gQKV, 256>>>(lnp, audio, cwq, cwk, cwv, cbq, cbk, cbv, qkvp, C_);
    fattn_k<<<gA, 256, attn_smem>>>(qkvp, amask, yp, TA_);
    hgemm_k<2><<<gC, 256>>>(yp, cwo, cbo, out, modp + 2*C_, C_, C_);

    // ---- MLP ----
    ln_mod_k<<<R_, 256>>>(out, modp, 3*C_, 4*C_, lnp);
    hgemm_k<1><<<gM, 256>>>(lnp, w1, b1, hp, nullptr, C_, M_);
    hgemm_k<2><<<gC, 256>>>(hp, w2, b2, out, modp + 5*C_, M_, C_);
}

// round 6
// speedup vs baseline: 8.5062x; 1.3873x over previous
#include <cuda_runtime.h>
#include <cuda_fp16.h>
#include <math.h>
#include <stdint.h>

#define T_  1024
#define B_  8
#define C_  1024
#define H_  16
#define D_  64
#define M_  4096
#define TA_ 1024
#define R_  (T_*B_)
#define SIXC (6*C_)

// ---------------- scratch (device globals) -----------------------------------
__device__ float  g_mod[B_*SIXC];
__device__ __half g_wh [16*1024*1024];     // packed fp16 weights
__device__ __half g_ah [(size_t)R_*C_];    // audio fp16
__device__ __half g_lnh[(size_t)R_*C_];    // ln+modulate fp16
__device__ __half g_qkv[(size_t)R_*3*C_];  // merged q|k|v fp16, row stride 3C
__device__ __half g_yh [(size_t)R_*C_];    // attention out fp16
__device__ __half g_hh [(size_t)R_*M_];    // mlp hidden fp16

// weight offsets inside g_wh (in elements)
#define WOFF_Q   (0)
#define WOFF_K   (1*1024*1024)
#define WOFF_V   (2*1024*1024)
#define WOFF_O   (3*1024*1024)
#define WOFF_CQ  (4*1024*1024)
#define WOFF_CK  (5*1024*1024)
#define WOFF_CV  (6*1024*1024)
#define WOFF_CO  (7*1024*1024)
#define WOFF_W1  (8*1024*1024)
#define WOFF_W2  (12*1024*1024)

// ---------------- helpers ----------------------------------------------------
__device__ __forceinline__ float gelu_tanh(float x) {
    float x3 = x*x*x;
    return 0.5f*x*(1.f + tanhf(0.7978845608028654f*(x + 0.044715f*x3)));
}
__device__ __forceinline__ uint32_t f2h2(float lo, float hi) {
    __half2 h = __floats2half2_rn(lo, hi);
    return *reinterpret_cast<uint32_t*>(&h);
}
__device__ __forceinline__ void mma_f16(float* d, const uint32_t* a, const uint32_t* b) {
    asm volatile(
        "mma.sync.aligned.m16n8k16.row.col.f32.f16.f16.f32 "
        "{%0,%1,%2,%3}, {%4,%5,%6,%7}, {%8,%9}, {%0,%1,%2,%3};\n"
        : "+f"(d[0]), "+f"(d[1]), "+f"(d[2]), "+f"(d[3])
        : "r"(a[0]), "r"(a[1]), "r"(a[2]), "r"(a[3]), "r"(b[0]), "r"(b[1]));
}
__device__ __forceinline__ void ldsm4(uint32_t* r, uint32_t addr) {
    asm volatile("ldmatrix.sync.aligned.m8n8.x4.shared.b16 {%0,%1,%2,%3}, [%4];"
        : "=r"(r[0]), "=r"(r[1]), "=r"(r[2]), "=r"(r[3]) : "r"(addr));
}
__device__ __forceinline__ void ldsm4t(uint32_t* r, uint32_t addr) {
    asm volatile("ldmatrix.sync.aligned.m8n8.x4.trans.shared.b16 {%0,%1,%2,%3}, [%4];"
        : "=r"(r[0]), "=r"(r[1]), "=r"(r[2]), "=r"(r[3]) : "r"(addr));
}
__device__ __forceinline__ void cpa16(uint32_t dst, const void* src) {
    asm volatile("cp.async.ca.shared.global [%0], [%1], 16;\n" :: "r"(dst), "l"(src));
}
__device__ __forceinline__ void cpa_commit() { asm volatile("cp.async.commit_group;\n"); }
__device__ __forceinline__ void cpa_wait1()  { asm volatile("cp.async.wait_group 1;\n"); }
__device__ __forceinline__ void cpa_wait0()  { asm volatile("cp.async.wait_group 0;\n"); }

// ---------------- small utility kernels --------------------------------------
__global__ void copy_k(const float* __restrict__ in, float* __restrict__ out) {
    int i = blockIdx.x*blockDim.x + threadIdx.x;
    ((float4*)out)[i] = ((const float4*)in)[i];
}
// fp32 -> fp16, 8 elems/thread
__global__ void f2h_k(const float* __restrict__ in, __half* __restrict__ out) {
    int i = (blockIdx.x*256 + threadIdx.x)*8;
    float4 a = *(const float4*)&in[i];
    float4 b = *(const float4*)&in[i+4];
    *(uint4*)&out[i] = make_uint4(f2h2(a.x,a.y), f2h2(a.z,a.w),
                                  f2h2(b.x,b.y), f2h2(b.z,b.w));
}

// ---------------- mod = silu(c) @ w_ada + b_ada ------------------------------
__global__ void mod_k(const float* __restrict__ c, const float* __restrict__ w,
                      const float* __restrict__ bias, float* __restrict__ mod) {
    __shared__ float sc[B_][C_];
    int tid = threadIdx.x;
    for (int i = tid; i < B_*C_; i += 256) {
        float v = c[i];
        sc[i>>10][i&1023] = v / (1.f + __expf(-v));
    }
    __syncthreads();
    int col = blockIdx.x*256 + tid;
    float acc[B_];
    #pragma unroll
    for (int b = 0; b < B_; b++) acc[b] = 0.f;
    for (int k = 0; k < C_; k++) {
        float wv = w[(size_t)k*SIXC + col];
        #pragma unroll
        for (int b = 0; b < B_; b++) acc[b] += sc[b][k]*wv;
    }
    float bb = bias[col];
    #pragma unroll
    for (int b = 0; b < B_; b++) mod[b*SIXC + col] = acc[b] + bb;
}

// ---------------- LN (no affine) + modulate -> fp16 --------------------------
// 256 threads, each owns 4 consecutive cols.
__global__ void ln_mod_k(const float* __restrict__ x, const float* __restrict__ mod,
                         int shiftOff, int scaleOff, __half* __restrict__ out) {
    int row = blockIdx.x;
    int b   = row & (B_-1);
    int tid = threadIdx.x;
    const float* xr = x + (size_t)row*C_;
    float4 v = *(const float4*)&xr[tid*4];
    float s  = v.x + v.y + v.z + v.w;
    float s2 = v.x*v.x + v.y*v.y + v.z*v.z + v.w*v.w;
    #pragma unroll
    for (int o = 16; o; o >>= 1) {
        s  += __shfl_xor_sync(0xffffffffu, s,  o);
        s2 += __shfl_xor_sync(0xffffffffu, s2, o);
    }
    __shared__ float red[2][8];
    int w = tid >> 5, ln = tid & 31;
    if (ln == 0) { red[0][w] = s; red[1][w] = s2; }
    __syncthreads();
    s = 0.f; s2 = 0.f;
    #pragma unroll
    for (int i = 0; i < 8; i++) { s += red[0][i]; s2 += red[1][i]; }
    float mu   = s * (1.f/C_);
    float var  = s2 * (1.f/C_) - mu*mu;
    float rstd = rsqrtf(var + 1e-6f);
    const float* sh = mod + b*SIXC + shiftOff + tid*4;
    const float* sc = mod + b*SIXC + scaleOff + tid*4;
    float4 shv = *(const float4*)sh;
    float4 scv = *(const float4*)sc;
    float m0 = (v.x-mu)*rstd*(1.f+scv.x) + shv.x;
    float m1 = (v.y-mu)*rstd*(1.f+scv.y) + shv.y;
    float m2 = (v.z-mu)*rstd*(1.f+scv.z) + shv.z;
    float m3 = (v.w-mu)*rstd*(1.f+scv.w) + shv.w;
    *(uint2*)&out[(size_t)row*C_ + tid*4] = make_uint2(f2h2(m0,m1), f2h2(m2,m3));
}

// ---------------- fp16 GEMM 128x128, BK=32, cp.async double buffer -----------
// As: per 16-k slice [row][8 u32 data], row stride SAW=12 u32 (48B)
// Bs: per 16-k slice [k][64 u32 data], row stride SBW=68 u32 (272B)
#define SAW 12
#define SBW 68
#define ABUF (2*128*SAW)     // u32 per buffer (2 k-slices)
#define BBUF (2*16*SBW)

template<int EPI, typename OT>
__device__ __forceinline__ void gemm_body(
    uint32_t* AsS, uint32_t* BsS,
    const __half* __restrict__ A, const __half* __restrict__ W,
    const float* __restrict__ bias, OT* __restrict__ out,
    const float* __restrict__ gate,
    int K, int N, int row0, int col0, size_t ostride, int ocol0)
{
    int tid  = threadIdx.x;
    int lane = tid & 31, wid = tid >> 5;
    int g    = lane >> 2, tig = lane & 3;
    int wm   = wid >> 2, wn = wid & 3;       // warp tile 64m x 32n

    uint32_t sA0 = (uint32_t)__cvta_generic_to_shared(AsS);
    uint32_t sB0 = (uint32_t)__cvta_generic_to_shared(BsS);

    float acc[4][4][4];
    #pragma unroll
    for (int i = 0; i < 4; i++)
        #pragma unroll
        for (int j = 0; j < 4; j++)
            #pragma unroll
            for (int q = 0; q < 4; q++) acc[i][j][q] = 0.f;

    // cp.async load of one 32-k chunk into buffer `bf`
    auto load_chunk = [&](int k0, int bf) {
        #pragma unroll
        for (int p = 0; p < 2; p++) {
            int idx = tid + p*256;
            int row = idx >> 2, q = idx & 3, ks = q >> 1, hs = q & 1;
            const __half* src = A + (size_t)(row0 + row)*K + k0 + ks*16 + hs*8;
            uint32_t dst = sA0 + (bf*ABUF + ks*128*SAW + row*SAW + hs*4)*4;
            cpa16(dst, src);
        }
        #pragma unroll
        for (int p = 0; p < 2; p++) {
            int idx = tid + p*256;
            int kr = idx >> 4, nc = idx & 15;
            const __half* src = W + (size_t)(k0 + kr)*N + col0 + nc*8;
            uint32_t dst = sB0 + (bf*BBUF + (kr>>4)*16*SBW + (kr&15)*SBW + nc*4)*4;
            cpa16(dst, src);
        }
        cpa_commit();
    };

    load_chunk(0, 0);

    int buf = 0;
    int nchunk = K >> 5;
    for (int ch = 0; ch < nchunk; ch++) {
        bool more = (ch + 1 < nchunk);
        if (more) { load_chunk((ch + 1)*32, buf ^ 1); cpa_wait1(); }
        else      { cpa_wait0(); }
        __syncthreads();

        #pragma unroll
        for (int ks = 0; ks < 2; ks++) {
            uint32_t sA = sA0 + (buf*ABUF + ks*128*SAW)*4;
            uint32_t sB = sB0 + (buf*BBUF + ks*16*SBW)*4;
            uint32_t af[4][4];
            #pragma unroll
            for (int mt = 0; mt < 4; mt++) {
                uint32_t addr = sA + ((wm*64 + mt*16 + (lane & 15))*SAW + ((lane >> 4) << 2))*4;
                ldsm4(af[mt], addr);
            }
            uint32_t bq[2][4];
            #pragma unroll
            for (int hf = 0; hf < 2; hf++) {
                uint32_t addr = sB + ((lane & 15)*SBW + (wn*16 + hf*8) + ((lane >> 4) << 2))*4;
                ldsm4t(bq[hf], addr);
            }
            #pragma unroll
            for (int mt = 0; mt < 4; mt++)
                #pragma unroll
                for (int nt = 0; nt < 4; nt++)
                    mma_f16(acc[mt][nt], af[mt], &bq[nt >> 1][(nt & 1)*2]);
        }
        __syncthreads();
        buf ^= 1;
    }

    #pragma unroll
    for (int mt = 0; mt < 4; mt++) {
        int rbase = row0 + wm*64 + mt*16 + g;
        #pragma unroll
        for (int half = 0; half < 2; half++) {
            int rr = rbase + 8*half;
            int bb = rr & (B_-1);
            OT* orow = out + (size_t)rr*ostride + ocol0;
            #pragma unroll
            for (int nt = 0; nt < 4; nt++) {
                int cl = col0 + wn*32 + nt*8 + 2*tig;
                float v0 = acc[mt][nt][2*half + 0] + bias[cl];
                float v1 = acc[mt][nt][2*half + 1] + bias[cl+1];
                if (EPI == 2) {
                    float* fr = (float*)orow;
                    fr[cl]   += gate[bb*SIXC + cl  ]*v0;
                    fr[cl+1] += gate[bb*SIXC + cl+1]*v1;
                } else if (EPI == 1) {
                    *(uint32_t*)&orow[cl] = f2h2(gelu_tanh(v0), gelu_tanh(v1));
                } else {
                    *(uint32_t*)&orow[cl] = f2h2(v0, v1);
                }
            }
        }
    }
}

template<int EPI, typename OT>
__global__ void __launch_bounds__(256, 2)
hgemm_k(const __half* __restrict__ A, const __half* __restrict__ W,
        const float* __restrict__ bias, OT* __restrict__ out,
        const float* __restrict__ gate, int K, int N) {
    __shared__ __align__(16) uint32_t As[2*ABUF];
    __shared__ __align__(16) uint32_t Bs[2*BBUF];
    gemm_body<EPI, OT>(As, Bs, A, W, bias, out, gate, K, N,
                       blockIdx.y*128, blockIdx.x*128, N, 0);
}

// merged q/k/v projection: grid.x = 24 (3 mats x 8 col-blocks); out stride 3C
__global__ void __launch_bounds__(256, 2)
hgemm_qkv_k(const __half* __restrict__ A0, const __half* __restrict__ A12,
            const __half* __restrict__ Wbase,
            const float* __restrict__ b0, const float* __restrict__ b1,
            const float* __restrict__ b2,
            __half* __restrict__ out, int woff0, int K) {
    __shared__ __align__(16) uint32_t As[2*ABUF];
    __shared__ __align__(16) uint32_t Bs[2*BBUF];
    int sel = blockIdx.x >> 3;
    int nb  = blockIdx.x & 7;
    const __half* A    = (sel == 0) ? A0 : A12;
    const __half* W    = Wbase + woff0 + sel*(C_*C_);
    const float* bias  = (sel == 0) ? b0 : (sel == 1) ? b1 : b2;
    gemm_body<0, __half>(As, Bs, A, W, bias, out, nullptr, K, C_,
                         blockIdx.y*128, nb*128, 3*C_, sel*C_);
}

// ---------------- fp16 tensor-core flash attention ---------------------------
// Qs/Ks/Vs/Ps: [row][32 u32 data], stride AQW=36 u32 (144B); Ssf fp32 stride 68
#define AQW 36
#define SSW 68
__global__ void __launch_bounds__(256, 2)
fattn_k(const __half* __restrict__ QKV, const int* __restrict__ mask,
        __half* __restrict__ Y, int Tk) {
    extern __shared__ uint32_t smu[];
    uint32_t* Qs = smu;
    uint32_t* Ks = Qs + 64*AQW;
    uint32_t* Vs = Ks + 64*AQW;
    uint32_t* Ps = Vs + 64*AQW;
    float*    Ssf  = (float*)(Ps + 64*AQW);
    float*    mrow = Ssf + 64*SSW;
    float*    lrow = mrow + 64;
    float*    srow = lrow + 64;
    int*      Ms   = (int*)(srow + 64);

    int tid  = threadIdx.x;
    int lane = tid & 31, wid = tid >> 5;
    int g    = lane >> 2, tig = lane & 3;
    int wm   = wid >> 1, wn = wid & 1;
    int q0 = blockIdx.x*64, h = blockIdx.y, b = blockIdx.z;
    size_t hoff = (size_t)h*D_;
    const int RS = 3*C_;
    const __half* Kp = QKV + C_;
    const __half* Vp = QKV + 2*C_;

    uint32_t vbase = (uint32_t)__cvta_generic_to_shared(Vs);

    // load Q tile: 64 rows x 64 half; thread -> (row=idx>>3, 8-half col chunk)
    #pragma unroll
    for (int p = 0; p < 2; p++) {
        int idx = tid + p*256;
        int r = idx >> 3, c8 = idx & 7;
        uint4 v = *(const uint4*)&QKV[((size_t)(q0+r)*B_ + b)*RS + hoff + c8*8];
        *(uint4*)&Qs[r*AQW + c8*4] = v;
    }
    if (tid < 64) { mrow[tid] = -1e30f; lrow[tid] = 0.f; }

    float oacc[4][4];
    #pragma unroll
    for (int i = 0; i < 4; i++)
        #pragma unroll
        for (int j = 0; j < 4; j++) oacc[i][j] = 0.f;
    __syncthreads();

    for (int k0 = 0; k0 < Tk; k0 += 64) {
        #pragma unroll
        for (int p = 0; p < 2; p++) {
            int idx = tid + p*256;
            int r = idx >> 3, c8 = idx & 7;
            size_t gi = ((size_t)(k0+r)*B_ + b)*RS + hoff + c8*8;
            *(uint4*)&Ks[r*AQW + c8*4] = *(const uint4*)&Kp[gi];
            *(uint4*)&Vs[r*AQW + c8*4] = *(const uint4*)&Vp[gi];
        }
        if (tid < 64) Ms[tid] = mask[(size_t)b*Tk + k0 + tid];
        __syncthreads();

        // ---- S = Q K^T ----
        float sacc[4][4];
        #pragma unroll
        for (int i = 0; i < 4; i++)
            #pragma unroll
            for (int j = 0; j < 4; j++) sacc[i][j] = 0.f;
        #pragma unroll
        for (int ks = 0; ks < 4; ks++) {
            uint32_t af[4];
            const uint32_t* qp = &Qs[(wm*16 + g)*AQW + ks*8 + tig];
            af[0] = qp[0]; af[1] = qp[8*AQW]; af[2] = qp[4]; af[3] = qp[8*AQW + 4];
            #pragma unroll
            for (int nt = 0; nt < 4; nt++) {
                int nr = wn*32 + nt*8 + g;
                uint32_t bf[2];
                bf[0] = Ks[nr*AQW + ks*8 + tig];
                bf[1] = Ks[nr*AQW + ks*8 + tig + 4];
                mma_f16(sacc[nt], af, bf);
            }
        }
        #pragma unroll
        for (int nt = 0; nt < 4; nt++) {
            int cc = wn*32 + nt*8 + 2*tig;
            int r0 = wm*16 + g;
            *(float2*)&Ssf[ r0     *SSW + cc] = make_float2(sacc[nt][0], sacc[nt][1]);
            *(float2*)&Ssf[(r0 + 8)*SSW + cc] = make_float2(sacc[nt][2], sacc[nt][3]);
        }
        __syncthreads();

        // ---- online softmax ----
        {
            int r  = tid >> 2, c0 = (tid & 3)*16;
            float s[16];
            #pragma unroll
            for (int j = 0; j < 16; j++)
                s[j] = Ms[c0 + j] ? -1e30f : Ssf[r*SSW + c0 + j]*0.125f;
            float mx = s[0];
            #pragma unroll
            for (int j = 1; j < 16; j++) mx = fmaxf(mx, s[j]);
            mx = fmaxf(mx, __shfl_xor_sync(0xffffffffu, mx, 1));
            mx = fmaxf(mx, __shfl_xor_sync(0xffffffffu, mx, 2));
            float mold = mrow[r];
            float mnew = fmaxf(mold, mx);
            float p[16];
            float rs = 0.f;
            #pragma unroll
            for (int j = 0; j < 16; j++) {
                p[j] = (s[j] > -1e29f) ? __expf(s[j] - mnew) : 0.f;
                rs += p[j];
            }
            uint32_t* pr = &Ps[r*AQW + (c0>>1)];
            #pragma unroll
            for (int j = 0; j < 8; j++) pr[j] = f2h2(p[2*j], p[2*j+1]);
            rs += __shfl_xor_sync(0xffffffffu, rs, 1);
            rs += __shfl_xor_sync(0xffffffffu, rs, 2);
            if ((tid & 3) == 0) {
                float scl = __expf(mold - mnew);
                lrow[r] = lrow[r]*scl + rs;
                mrow[r] = mnew;
                srow[r] = scl;
            }
        }
        __syncthreads();

        // ---- O = O*scale + P @ V ----
        float s0 = srow[wm*16 + g];
        float s1 = srow[wm*16 + g + 8];
        #pragma unroll
        for (int nt = 0; nt < 4; nt++) {
            oacc[nt][0] *= s0; oacc[nt][1] *= s0;
            oacc[nt][2] *= s1; oacc[nt][3] *= s1;
        }
        #pragma unroll
        for (int ks = 0; ks < 4; ks++) {
            uint32_t af[4];
            const uint32_t* pp = &Ps[(wm*16 + g)*AQW + ks*8 + tig];
            af[0] = pp[0]; af[1] = pp[8*AQW]; af[2] = pp[4]; af[3] = pp[8*AQW + 4];
            uint32_t bq[2][4];
            #pragma unroll
            for (int hf = 0; hf < 2; hf++) {
                uint32_t addr = vbase +
                    ((ks*16 + (lane & 15))*AQW + (wn*16 + hf*8) + ((lane >> 4) << 2))*4;
                ldsm4t(bq[hf], addr);
            }
            #pragma unroll
            for (int nt = 0; nt < 4; nt++)
                mma_f16(oacc[nt], af, &bq[nt >> 1][(nt & 1)*2]);
        }
        __syncthreads();
    }

    // epilogue: O / l -> fp16
    float inv0 = 1.f / lrow[wm*16 + g];
    float inv1 = 1.f / lrow[wm*16 + g + 8];
    int r0 = q0 + wm*16 + g;
    #pragma unroll
    for (int nt = 0; nt < 4; nt++) {
        int dd = wn*32 + nt*8 + 2*tig;
        *(uint32_t*)&Y[((size_t) r0     *B_ + b)*C_ + hoff + dd] =
            f2h2(oacc[nt][0]*inv0, oacc[nt][1]*inv0);
        *(uint32_t*)&Y[((size_t)(r0 + 8)*B_ + b)*C_ + hoff + dd] =
            f2h2(oacc[nt][2]*inv1, oacc[nt][3]*inv1);
    }
}

// ---------------- launch -----------------------------------------------------
extern "C" void kernel_launch(void* const* d_in, const int* in_sizes, int n_in,
                              void* d_out, int out_size) {
    const float* x     = (const float*)d_in[0];
    const float* c     = (const float*)d_in[1];
    const int*   pmask = (const int*)  d_in[2];
    const float* audio = (const float*)d_in[3];
    const int*   amask = (const int*)  d_in[4];
    const float* w_ada = (const float*)d_in[5];
    const float* b_ada = (const float*)d_in[6];
    const float* wq = (const float*)d_in[7];   const float* bq = (const float*)d_in[8];
    const float* wk = (const float*)d_in[9];   const float* bk = (const float*)d_in[10];
    const float* wv = (const float*)d_in[11];  const float* bv = (const float*)d_in[12];
    const float* wo = (const float*)d_in[13];  const float* bo = (const float*)d_in[14];
    const float* cwq = (const float*)d_in[15]; const float* cbq = (const float*)d_in[16];
    const float* cwk = (const float*)d_in[17]; const float* cbk = (const float*)d_in[18];
    const float* cwv = (const float*)d_in[19]; const float* cbv = (const float*)d_in[20];
    const float* cwo = (const float*)d_in[21]; const float* cbo = (const float*)d_in[22];
    const float* w1 = (const float*)d_in[23];  const float* b1 = (const float*)d_in[24];
    const float* w2 = (const float*)d_in[25];  const float* b2 = (const float*)d_in[26];
    float* out = (float*)d_out;

    float  *modp;
    __half *whp, *ahp, *lnp, *qkvp, *yp, *hp;
    cudaGetSymbolAddress((void**)&modp, g_mod);
    cudaGetSymbolAddress((void**)&whp,  g_wh);
    cudaGetSymbolAddress((void**)&ahp,  g_ah);
    cudaGetSymbolAddress((void**)&lnp,  g_lnh);
    cudaGetSymbolAddress((void**)&qkvp, g_qkv);
    cudaGetSymbolAddress((void**)&yp,   g_yh);
    cudaGetSymbolAddress((void**)&hp,   g_hh);

    int attn_smem = (4*64*AQW + 64*SSW + 3*64 + 64)*sizeof(uint32_t);
    cudaFuncSetAttribute(fattn_k, cudaFuncAttributeMaxDynamicSharedMemorySize, attn_smem);

    dim3 gQKV(24, 64);
    dim3 gC(8, 64);
    dim3 gM(32, 64);
    dim3 gA(T_/64, H_, B_);

    // residual init + adaLN params + fp16 conversions
    copy_k<<<(R_*C_)/1024, 256>>>(x, out);
    mod_k<<<SIXC/256, 256>>>(c, w_ada, b_ada, modp);
    f2h_k<<<(C_*C_)/2048, 256>>>(wq,  whp + WOFF_Q);
    f2h_k<<<(C_*C_)/2048, 256>>>(wk,  whp + WOFF_K);
    f2h_k<<<(C_*C_)/2048, 256>>>(wv,  whp + WOFF_V);
    f2h_k<<<(C_*C_)/2048, 256>>>(wo,  whp + WOFF_O);
    f2h_k<<<(C_*C_)/2048, 256>>>(cwq, whp + WOFF_CQ);
    f2h_k<<<(C_*C_)/2048, 256>>>(cwk, whp + WOFF_CK);
    f2h_k<<<(C_*C_)/2048, 256>>>(cwv, whp + WOFF_CV);
    f2h_k<<<(C_*C_)/2048, 256>>>(cwo, whp + WOFF_CO);
    f2h_k<<<(C_*M_)/2048, 256>>>(w1,  whp + WOFF_W1);
    f2h_k<<<(M_*C_)/2048, 256>>>(w2,  whp + WOFF_W2);
    f2h_k<<<(R_*C_)/2048, 256>>>(audio, ahp);

    // ---- self attention ----
    ln_mod_k<<<R_, 256>>>(out, modp, 0, C_, lnp);
    hgemm_qkv_k<<<gQKV, 256>>>(lnp, lnp, whp, bq, bk, bv, qkvp, WOFF_Q, C_);
    fattn_k<<<gA, 256, attn_smem>>>(qkvp, pmask, yp, T_);
    hgemm_k<2, float><<<gC, 256>>>(yp, whp + WOFF_O, bo, out, modp + 2*C_, C_, C_);

    // ---- cross attention (reuses msa shift/scale/gate) ----
    ln_mod_k<<<R_, 256>>>(out, modp, 0, C_, lnp);
    hgemm_qkv_k<<<gQKV, 256>>>(lnp, ahp, whp, cbq, cbk, cbv, qkvp, WOFF_CQ, C_);
    fattn_k<<<gA, 256, attn_smem>>>(qkvp, amask, yp, TA_);
    hgemm_k<2, float><<<gC, 256>>>(yp, whp + WOFF_CO, cbo, out, modp + 2*C_, C_, C_);

    // ---- MLP ----
    ln_mod_k<<<R_, 256>>>(out, modp, 3*C_, 4*C_, lnp);
    hgemm_k<1, __half><<<gM, 256>>>(lnp, whp + WOFF_W1, b1, hp, nullptr, C_, M_);
    hgemm_k<2, float><<<gC, 256>>>(hp, whp + WOFF_W2, b2, out, modp + 5*C_, M_, C_);
}